// round 8
// baseline (speedup 1.0000x reference)
#include <cuda_runtime.h>
#include <cuda_fp16.h>
#include <cstdint>

// ---------------- problem constants ----------------
#define B_SZ   8
#define T_LEN  4096
#define D_INP  256
#define D_OUTP 256
#define N_ST   512
#define M_TOT  (B_SZ * T_LEN)      // 32768
#define NBU    (2 * N_ST)          // 1024
#define KCAT   (NBU + D_INP)       // 1280
#define CHUNK  128
#define NCHUNK (T_LEN / CHUNK)     // 32

// ---------------- device scratch ----------------
// A2 layout: cols [0,1024) = X interleaved (2n = xr_n, 2n+1 = xi_n), cols [1024,1280) = u
__device__ __half g_A2[(size_t)M_TOT * KCAT];
__device__ __half g_B1[NBU * D_INP];             // gamma-scaled B, interleaved rows
__device__ __half g_W2[D_OUTP * KCAT];           // K-interleaved [2Cr/-2Ci | D]
__device__ float2 g_lam [N_ST];
__device__ float2 g_lamL[N_ST];
__device__ float2 g_lamPow[CHUNK * N_ST];        // lam^(t+1), [t][n]
__device__ float2 g_F    [B_SZ * NCHUNK * N_ST];
__device__ float2 g_carry[B_SZ * NCHUNK * N_ST];

// ---------------- helpers ----------------
__device__ __forceinline__ uint32_t smem_u32(const void* p) {
    uint32_t a;
    asm("{ .reg .u64 t; cvta.to.shared.u64 t, %1; cvt.u32.u64 %0, t; }" : "=r"(a) : "l"(p));
    return a;
}

#define CP_ASYNC16(dst, src) \
    asm volatile("cp.async.cg.shared.global [%0], [%1], 16;" :: "r"(dst), "l"(src))
#define CP_COMMIT() asm volatile("cp.async.commit_group;")
#define CP_WAIT2()  asm volatile("cp.async.wait_group 2;")
#define CP_WAIT0()  asm volatile("cp.async.wait_group 0;")

#define LDSM4(r0, r1, r2, r3, addr) \
    asm volatile("ldmatrix.sync.aligned.m8n8.x4.shared.b16 {%0,%1,%2,%3}, [%4];" \
        : "=r"(r0), "=r"(r1), "=r"(r2), "=r"(r3) : "r"(addr))

#define MMA16816(d, a, b0, b1) \
    asm volatile("mma.sync.aligned.m16n8k16.row.col.f32.f16.f16.f32 " \
        "{%0,%1,%2,%3}, {%4,%5,%6,%7}, {%8,%9}, {%0,%1,%2,%3};" \
        : "+f"(d[0]), "+f"(d[1]), "+f"(d[2]), "+f"(d[3]) \
        : "r"(a[0]), "r"(a[1]), "r"(a[2]), "r"(a[3]), "r"(b0), "r"(b1))

// ---------------- setup kernels ----------------
__global__ void k_setup(const float* __restrict__ nu_log,
                        const float* __restrict__ theta_log) {
    int n = blockIdx.x * blockDim.x + threadIdx.x;
    if (n >= N_ST) return;
    float lm = expf(-expf(nu_log[n]));
    float th = expf(theta_log[n]);
    float2 lam = make_float2(lm * cosf(th), lm * sinf(th));
    g_lam[n] = lam;
    float2 p = lam;
#pragma unroll
    for (int i = 0; i < 7; i++) {
        float2 q;
        q.x = p.x * p.x - p.y * p.y;
        q.y = 2.0f * p.x * p.y;
        p = q;
    }
    g_lamL[n] = p;
}

__global__ void k_lamPow() {
    int idx = blockIdx.x * blockDim.x + threadIdx.x;
    if (idx >= CHUNK * N_ST) return;
    int t = idx >> 9, n = idx & (N_ST - 1);
    float2 base = g_lam[n];
    float2 r = make_float2(1.0f, 0.0f);
    int e = t + 1;
    while (e) {
        if (e & 1) {
            float2 q;
            q.x = r.x * base.x - r.y * base.y;
            q.y = r.x * base.y + r.y * base.x;
            r = q;
        }
        float2 s;
        s.x = base.x * base.x - base.y * base.y;
        s.y = 2.0f * base.x * base.y;
        base = s;
        e >>= 1;
    }
    g_lamPow[t * N_ST + n] = r;
}

// interleaved rows: row 2n = gamma*Br[n], row 2n+1 = gamma*Bi[n]
__global__ void k_cvtB(const float* __restrict__ gamma_log,
                       const float* __restrict__ Br,
                       const float* __restrict__ Bi) {
    int idx = blockIdx.x * blockDim.x + threadIdx.x;
    if (idx >= NBU * D_INP) return;
    int nn = idx / D_INP, i = idx % D_INP;
    int n = nn >> 1;
    float g = expf(gamma_log[n]);
    float v = g * (((nn & 1) == 0) ? Br[n * D_INP + i] : Bi[n * D_INP + i]);
    g_B1[idx] = __float2half_rn(v);
}

// K-interleaved weights: k=2n -> 2Cr[o][n], k=2n+1 -> -2Ci[o][n], k>=1024 -> D
__global__ void k_buildW2(const float* __restrict__ Cr,
                          const float* __restrict__ Ci,
                          const float* __restrict__ Dm) {
    int idx = blockIdx.x * blockDim.x + threadIdx.x;
    if (idx >= D_OUTP * KCAT) return;
    int o = idx / KCAT, k = idx % KCAT;
    float v;
    if (k < NBU) {
        int n = k >> 1;
        v = ((k & 1) == 0) ? 2.0f * Cr[o * N_ST + n] : -2.0f * Ci[o * N_ST + n];
    } else {
        v = Dm[o * D_INP + (k - NBU)];
    }
    g_W2[idx] = __float2half_rn(v);
}

__global__ void k_cvtU(const float* __restrict__ u) {
    int idx = blockIdx.x * blockDim.x + threadIdx.x;
    if (idx >= M_TOT * D_INP / 2) return;
    int m = idx / (D_INP / 2), i = (idx % (D_INP / 2)) * 2;
    float2 v = *(const float2*)(u + (size_t)m * D_INP + i);
    __half2 h = __floats2half2_rn(v.x, v.y);
    *(__half2*)(g_A2 + (size_t)m * KCAT + NBU + i) = h;
}

// ---------------- GEMM geometry: CTA 128(M) x 256(N), BK=32 ----------------
// 8 warps as 2(m) x 4(n); warp tile 64x64; mma.m16n8k16; acc[4][8][4].
#define BK       32
#define PADK     40                       // padded k-stride (elems)
#define TILE_A_B (128 * PADK * 2)         // 10240 B
#define TILE_B_B (256 * PADK * 2)         // 20480 B
#define STAGE_B  (TILE_A_B + TILE_B_B)    // 30720 B
#define STAGES   4
#define SMEM_GEMM (STAGES * STAGE_B)      // 122880 B
#define SMEM_GEMM2 (SMEM_GEMM + N_ST * 8) // + carry row (4 KB)

__device__ __forceinline__ void gemm_mainloop(
    uint32_t sb, const __half* A0, const __half* B0,
    int K, int lda, int ldb, float acc[4][8][4],
    int tid, int wm, int wn, int lid) {

    const int NC = K / BK;

    auto issue_load = [&](int c) {
        const int s = c % STAGES;
        const uint32_t stb = sb + s * STAGE_B;
        const int k0 = c * BK;
#pragma unroll
        for (int r = 0; r < 2; r++) {                // A: 512 chunks
            int idx = tid + r * 256;
            int row = idx >> 2, ch = idx & 3;
            uint32_t soff = (uint32_t)(row * (PADK * 2) + ch * 16);
            CP_ASYNC16(stb + soff, A0 + (size_t)row * lda + k0 + ch * 8);
        }
#pragma unroll
        for (int r = 0; r < 4; r++) {                // B: 1024 chunks
            int idx = tid + r * 256;
            int row = idx >> 2, ch = idx & 3;
            uint32_t soff = (uint32_t)(row * (PADK * 2) + ch * 16);
            CP_ASYNC16(stb + TILE_A_B + soff, B0 + (size_t)row * ldb + k0 + ch * 8);
        }
        CP_COMMIT();
    };

    const int aRow = lid & 15;
    const int aCol = (lid >> 4) << 3;
    const int bRow = (lid & 7) + ((lid >> 4) << 3);
    const int bCol = ((lid >> 3) & 1) << 3;

    issue_load(0);
    issue_load(1);
    issue_load(2);

    for (int c = 0; c < NC; c++) {
        CP_WAIT2();
        __syncthreads();
        if (c + 3 < NC) issue_load(c + 3);
        else            CP_COMMIT();

        const uint32_t stb = sb + (c % STAGES) * STAGE_B;
        const uint32_t sA = stb;
        const uint32_t sB = stb + TILE_A_B;

#pragma unroll
        for (int kk = 0; kk < BK; kk += 16) {
            uint32_t a[4][4], b[4][4];
#pragma unroll
            for (int mf = 0; mf < 4; mf++) {
                uint32_t ad = sA + (uint32_t)((wm * 64 + mf * 16 + aRow) * (PADK * 2) + (kk + aCol) * 2);
                LDSM4(a[mf][0], a[mf][1], a[mf][2], a[mf][3], ad);
            }
#pragma unroll
            for (int p = 0; p < 4; p++) {
                uint32_t bd = sB + (uint32_t)((wn * 64 + p * 16 + bRow) * (PADK * 2) + (kk + bCol) * 2);
                LDSM4(b[p][0], b[p][1], b[p][2], b[p][3], bd);
            }
#pragma unroll
            for (int mf = 0; mf < 4; mf++)
#pragma unroll
                for (int nf = 0; nf < 8; nf++)
                    MMA16816(acc[mf][nf], a[mf], b[nf >> 1][(nf & 1) * 2], b[nf >> 1][(nf & 1) * 2 + 1]);
        }
        __syncthreads();
    }
    CP_WAIT0();
}

// ---------------- GEMM1 + fused chunk-local two-segment scan ----------------
#define SCAN_STRIDE 264
#define SMEM_SCAN   (128 * SCAN_STRIDE * 4)   // 135168 B

__global__ __launch_bounds__(256, 1)
void gemm1_scan(const __half* __restrict__ A,
                const __half* __restrict__ B) {
    extern __shared__ char smem[];
    const uint32_t sb = smem_u32(smem);
    const int tid = threadIdx.x;
    const int wid = tid >> 5, lid = tid & 31;
    const int m0 = blockIdx.y * 128;
    const int n0 = blockIdx.x * 256;
    const int wm = wid >> 2, wn = wid & 3;

    float acc[4][8][4];
#pragma unroll
    for (int i = 0; i < 4; i++)
#pragma unroll
        for (int j = 0; j < 8; j++)
#pragma unroll
            for (int q = 0; q < 4; q++) acc[i][j][q] = 0.0f;

    gemm_mainloop(sb, A + (size_t)m0 * KCAT, B + (size_t)n0 * D_INP,
                  D_INP, KCAT, D_INP, acc, tid, wm, wn, lid);

    __syncthreads();            // pipeline smem dead, reuse for scan buffer

    float* sc = (float*)smem;   // [128][SCAN_STRIDE]
    const int gid = lid >> 2, tig = lid & 3;
#pragma unroll
    for (int mf = 0; mf < 4; mf++) {
        const int row = wm * 64 + mf * 16 + gid;
#pragma unroll
        for (int nf = 0; nf < 8; nf++) {
            const int col = wn * 64 + nf * 8 + tig * 2;
            *(float2*)(sc + row * SCAN_STRIDE + col) =
                make_float2(acc[mf][nf][0], acc[mf][nf][1]);
            *(float2*)(sc + (row + 8) * SCAN_STRIDE + col) =
                make_float2(acc[mf][nf][2], acc[mf][nf][3]);
        }
    }
    __syncthreads();

    // two-segment in-place scan: threads 0-127 do t=0..63, 128-255 do t=64..127
    {
        const int s = tid & 127;
        const int np = (n0 >> 1) + s;
        const float2 lam = g_lam[np];
        const int tstart = (tid < 128) ? 0 : 64;
        float* p = sc + tstart * SCAN_STRIDE + 2 * s;
        float xr = 0.0f, xi = 0.0f;
#pragma unroll 4
        for (int t = 0; t < 64; t++) {
            float2 bu = *(const float2*)p;
            float nxr = fmaf(lam.x, xr, fmaf(-lam.y, xi, bu.x));
            float nxi = fmaf(lam.x, xi, fmaf(lam.y, xr, bu.y));
            xr = nxr; xi = nxi;
            *(float2*)p = make_float2(xr, xi);
            p += SCAN_STRIDE;
        }
    }
    __syncthreads();

    // parallel combine + fp16 output: x_t += lam^(t-63) * x63 for t>=64
    const int bb = m0 >> 12;                 // / T_LEN
    const int cc = (m0 & (T_LEN - 1)) >> 7;  // / CHUNK
    __half* outb = g_A2 + (size_t)m0 * KCAT + n0;   // col byte-pair base = 2*(n0>>1)
#pragma unroll 4
    for (int r = 0; r < 64; r++) {
        int idx = r * 256 + tid;
        int t = idx >> 7, s = idx & 127;
        float2 v = *(const float2*)(sc + t * SCAN_STRIDE + 2 * s);
        if (t >= 64) {
            float2 x63 = *(const float2*)(sc + 63 * SCAN_STRIDE + 2 * s);
            float2 f = g_lamPow[(t - 64) * N_ST + (n0 >> 1) + s];
            v.x += f.x * x63.x - f.y * x63.y;
            v.y += f.x * x63.y + f.y * x63.x;
        }
        *(__half2*)(outb + (size_t)t * KCAT + 2 * s) = __floats2half2_rn(v.x, v.y);
    }
    // chunk final F = x127 + lam^64 * x63
    if (tid >= 128) {
        int s = tid - 128;
        int np = (n0 >> 1) + s;
        float2 x127 = *(const float2*)(sc + 127 * SCAN_STRIDE + 2 * s);
        float2 x63  = *(const float2*)(sc + 63 * SCAN_STRIDE + 2 * s);
        float2 f = g_lamPow[63 * N_ST + np];
        g_F[(bb * NCHUNK + cc) * N_ST + np] =
            make_float2(x127.x + f.x * x63.x - f.y * x63.y,
                        x127.y + f.x * x63.y + f.y * x63.x);
    }
}

// ---------------- GEMM2 with fused carry correction ----------------
// y[M,256] = corrected([X|u]) @ W2^T ; correction x += lamPow[t]*carry applied
// to the fp16 A-tile in smem before ldmatrix (k<1024 only).
__global__ __launch_bounds__(256, 1)
void gemm2_out(const __half* __restrict__ A,
               const __half* __restrict__ Bw,
               float* __restrict__ C) {
    extern __shared__ char smem[];
    const uint32_t sb = smem_u32(smem);
    const int tid = threadIdx.x;
    const int wid = tid >> 5, lid = tid & 31;
    const int m0 = blockIdx.y * 128;
    const int wm = wid >> 2, wn = wid & 3;

    const int bb = m0 >> 12;
    const int cc = (m0 & (T_LEN - 1)) >> 7;
    const bool do_corr = (cc != 0);

    float2* scarry = (float2*)(smem + SMEM_GEMM);
    if (do_corr) {
        const float2* csrc = g_carry + (bb * NCHUNK + cc) * N_ST;
#pragma unroll
        for (int i = tid; i < N_ST; i += 256) scarry[i] = csrc[i];
    }

    float acc[4][8][4];
#pragma unroll
    for (int i = 0; i < 4; i++)
#pragma unroll
        for (int j = 0; j < 8; j++)
#pragma unroll
            for (int q = 0; q < 4; q++) acc[i][j][q] = 0.0f;

    const __half* A0 = A + (size_t)m0 * KCAT;
    const int NC = KCAT / BK;   // 40

    auto issue_load = [&](int c) {
        const int s = c % STAGES;
        const uint32_t stb = sb + s * STAGE_B;
        const int k0 = c * BK;
#pragma unroll
        for (int r = 0; r < 2; r++) {
            int idx = tid + r * 256;
            int row = idx >> 2, ch = idx & 3;
            uint32_t soff = (uint32_t)(row * (PADK * 2) + ch * 16);
            CP_ASYNC16(stb + soff, A0 + (size_t)row * KCAT + k0 + ch * 8);
        }
#pragma unroll
        for (int r = 0; r < 4; r++) {
            int idx = tid + r * 256;
            int row = idx >> 2, ch = idx & 3;
            uint32_t soff = (uint32_t)(row * (PADK * 2) + ch * 16);
            CP_ASYNC16(stb + TILE_A_B + soff, Bw + (size_t)row * KCAT + k0 + ch * 8);
        }
        CP_COMMIT();
    };

    const int aRow = lid & 15;
    const int aCol = (lid >> 4) << 3;
    const int bRow = (lid & 7) + ((lid >> 4) << 3);
    const int bCol = ((lid >> 3) & 1) << 3;

    issue_load(0);
    issue_load(1);
    issue_load(2);

    for (int c = 0; c < NC; c++) {
        CP_WAIT2();
        __syncthreads();
        if (c + 3 < NC) issue_load(c + 3);
        else            CP_COMMIT();

        char* stp = smem + (c % STAGES) * STAGE_B;

        // fused carry correction on the A tile (states n = c*16 .. c*16+15)
        if (do_corr && c < (NBU / BK)) {
            const int n0s = c << 4;
#pragma unroll
            for (int j = 0; j < 8; j++) {
                int idx = tid * 8 + j;              // 0..2047
                int row = idx >> 4, st = idx & 15;
                __half2* hp = (__half2*)(stp + row * (PADK * 2) + st * 4);
                float2 xv = __half22float2(*hp);
                float2 f  = g_lamPow[row * N_ST + n0s + st];
                float2 cr = scarry[n0s + st];
                xv.x += f.x * cr.x - f.y * cr.y;
                xv.y += f.x * cr.y + f.y * cr.x;
                *hp = __floats2half2_rn(xv.x, xv.y);
            }
            __syncthreads();
        }

        const uint32_t stb = sb + (c % STAGES) * STAGE_B;
        const uint32_t sA = stb;
        const uint32_t sB = stb + TILE_A_B;

#pragma unroll
        for (int kk = 0; kk < BK; kk += 16) {
            uint32_t a[4][4], b[4][4];
#pragma unroll
            for (int mf = 0; mf < 4; mf++) {
                uint32_t ad = sA + (uint32_t)((wm * 64 + mf * 16 + aRow) * (PADK * 2) + (kk + aCol) * 2);
                LDSM4(a[mf][0], a[mf][1], a[mf][2], a[mf][3], ad);
            }
#pragma unroll
            for (int p = 0; p < 4; p++) {
                uint32_t bd = sB + (uint32_t)((wn * 64 + p * 16 + bRow) * (PADK * 2) + (kk + bCol) * 2);
                LDSM4(b[p][0], b[p][1], b[p][2], b[p][3], bd);
            }
#pragma unroll
            for (int mf = 0; mf < 4; mf++)
#pragma unroll
                for (int nf = 0; nf < 8; nf++)
                    MMA16816(acc[mf][nf], a[mf], b[nf >> 1][(nf & 1) * 2], b[nf >> 1][(nf & 1) * 2 + 1]);
        }
        __syncthreads();
    }
    CP_WAIT0();

    const int gid = lid >> 2, tig = lid & 3;
#pragma unroll
    for (int mf = 0; mf < 4; mf++) {
        const int row = m0 + wm * 64 + mf * 16 + gid;
#pragma unroll
        for (int nf = 0; nf < 8; nf++) {
            const int col = wn * 64 + nf * 8 + tig * 2;
            *(float2*)(C + (size_t)row * D_OUTP + col) =
                make_float2(acc[mf][nf][0], acc[mf][nf][1]);
            *(float2*)(C + (size_t)(row + 8) * D_OUTP + col) =
                make_float2(acc[mf][nf][2], acc[mf][nf][3]);
        }
    }
}

// ---------------- chunk-level prefix over finals ----------------
__global__ void k_chunk_prefix() {
    int id = blockIdx.x * blockDim.x + threadIdx.x;
    if (id >= B_SZ * N_ST) return;
    int n = id & (N_ST - 1);
    int b = id >> 9;
    float2 lamL = g_lamL[n];
    float sr = 0.0f, si = 0.0f;
#pragma unroll
    for (int c = 0; c < NCHUNK; c++) {
        int idx = (b * NCHUNK + c) * N_ST + n;
        g_carry[idx] = make_float2(sr, si);
        float2 f = g_F[idx];
        float nsr = fmaf(lamL.x, sr, fmaf(-lamL.y, si, f.x));
        float nsi = fmaf(lamL.x, si, fmaf(lamL.y, sr, f.y));
        sr = nsr; si = nsi;
    }
}

// ---------------- launch ----------------
extern "C" void kernel_launch(void* const* d_in, const int* in_sizes, int n_in,
                              void* d_out, int out_size) {
    const float* u_in      = (const float*)d_in[0];
    const float* nu_log    = (const float*)d_in[1];
    const float* theta_log = (const float*)d_in[2];
    const float* gamma_log = (const float*)d_in[3];
    const float* B_real    = (const float*)d_in[4];
    const float* B_imag    = (const float*)d_in[5];
    const float* C_real    = (const float*)d_in[6];
    const float* C_imag    = (const float*)d_in[7];
    const float* Dm        = (const float*)d_in[8];
    float* y = (float*)d_out;

    __half *a2, *b1, *w2;
    cudaGetSymbolAddress((void**)&a2, g_A2);
    cudaGetSymbolAddress((void**)&b1, g_B1);
    cudaGetSymbolAddress((void**)&w2, g_W2);

    cudaFuncSetAttribute(gemm1_scan,
                         cudaFuncAttributeMaxDynamicSharedMemorySize, SMEM_SCAN);
    cudaFuncSetAttribute(gemm2_out,
                         cudaFuncAttributeMaxDynamicSharedMemorySize, SMEM_GEMM2);

    // setup / conversions
    k_setup<<<2, 256>>>(nu_log, theta_log);
    k_lamPow<<<(CHUNK * N_ST + 255) / 256, 256>>>();
    k_cvtB<<<(NBU * D_INP + 255) / 256, 256>>>(gamma_log, B_real, B_imag);
    k_buildW2<<<(D_OUTP * KCAT + 255) / 256, 256>>>(C_real, C_imag, Dm);
    k_cvtU<<<(M_TOT * D_INP / 2 + 255) / 256, 256>>>(u_in);

    // GEMM1 + chunk-local scan: writes X_local (fp16) into A2 and chunk finals
    {
        dim3 grid(NBU / 256, M_TOT / 128);
        gemm1_scan<<<grid, 256, SMEM_SCAN>>>(a2 + NBU, b1);
    }

    // chunk prefix (produces carries consumed by gemm2's fused correction)
    k_chunk_prefix<<<(B_SZ * N_ST + 255) / 256, 256>>>();

    // GEMM 2 (+carry correction fused): y[M,256] = corrected([X|u]) @ W2^T
    {
        dim3 grid(1, M_TOT / 128);
        gemm2_out<<<grid, 256, SMEM_GEMM2>>>(a2, w2, y);
    }
}

// round 9
// speedup vs baseline: 1.4620x; 1.4620x over previous
#include <cuda_runtime.h>
#include <cuda_fp16.h>
#include <cstdint>

// ---------------- problem constants ----------------
#define B_SZ   8
#define T_LEN  4096
#define D_INP  256
#define D_OUTP 256
#define N_ST   512
#define M_TOT  (B_SZ * T_LEN)      // 32768
#define NBU    (2 * N_ST)          // 1024
#define KCAT   (NBU + D_INP)       // 1280
#define CHUNK  128
#define NCHUNK (T_LEN / CHUNK)     // 32

// ---------------- device scratch ----------------
// A2 layout: cols [0,1024) = X interleaved (2n = xr_n, 2n+1 = xi_n), cols [1024,1280) = u
__device__ __half g_A2[(size_t)M_TOT * KCAT];
__device__ __half g_B1[NBU * D_INP];             // gamma-scaled B, interleaved rows
__device__ __half g_W2[D_OUTP * KCAT];           // K-interleaved [2Cr/-2Ci | D]
__device__ float2 g_lam [N_ST];
__device__ float2 g_lamL[N_ST];
__device__ float2 g_F    [B_SZ * NCHUNK * N_ST];
__device__ float2 g_carry[B_SZ * NCHUNK * N_ST];

// ---------------- helpers ----------------
__device__ __forceinline__ uint32_t smem_u32(const void* p) {
    uint32_t a;
    asm("{ .reg .u64 t; cvta.to.shared.u64 t, %1; cvt.u32.u64 %0, t; }" : "=r"(a) : "l"(p));
    return a;
}

#define CP_ASYNC16(dst, src) \
    asm volatile("cp.async.cg.shared.global [%0], [%1], 16;" :: "r"(dst), "l"(src))
#define CP_COMMIT() asm volatile("cp.async.commit_group;")
#define CP_WAIT2()  asm volatile("cp.async.wait_group 2;")
#define CP_WAIT0()  asm volatile("cp.async.wait_group 0;")

#define LDSM4(r0, r1, r2, r3, addr) \
    asm volatile("ldmatrix.sync.aligned.m8n8.x4.shared.b16 {%0,%1,%2,%3}, [%4];" \
        : "=r"(r0), "=r"(r1), "=r"(r2), "=r"(r3) : "r"(addr))

#define MMA16816(d, a, b0, b1) \
    asm volatile("mma.sync.aligned.m16n8k16.row.col.f32.f16.f16.f32 " \
        "{%0,%1,%2,%3}, {%4,%5,%6,%7}, {%8,%9}, {%0,%1,%2,%3};" \
        : "+f"(d[0]), "+f"(d[1]), "+f"(d[2]), "+f"(d[3]) \
        : "r"(a[0]), "r"(a[1]), "r"(a[2]), "r"(a[3]), "r"(b0), "r"(b1))

// ---------------- setup kernels ----------------
__global__ void k_setup(const float* __restrict__ nu_log,
                        const float* __restrict__ theta_log) {
    int n = blockIdx.x * blockDim.x + threadIdx.x;
    if (n >= N_ST) return;
    float lm = expf(-expf(nu_log[n]));
    float th = expf(theta_log[n]);
    float2 lam = make_float2(lm * cosf(th), lm * sinf(th));
    g_lam[n] = lam;
    float2 p = lam;
#pragma unroll
    for (int i = 0; i < 7; i++) {
        float2 q;
        q.x = p.x * p.x - p.y * p.y;
        q.y = 2.0f * p.x * p.y;
        p = q;
    }
    g_lamL[n] = p;
}

// merged weight prep:
//   idx < NBU*D_INP:         B1 (interleaved rows: 2n=gamma*Br, 2n+1=gamma*Bi)
//   else:                    W2 (K-interleaved [2Cr/-2Ci | D])
#define B1_ELEMS (NBU * D_INP)
#define W2_ELEMS (D_OUTP * KCAT)
__global__ void k_prepW(const float* __restrict__ gamma_log,
                        const float* __restrict__ Br,
                        const float* __restrict__ Bi,
                        const float* __restrict__ Cr,
                        const float* __restrict__ Ci,
                        const float* __restrict__ Dm) {
    int idx = blockIdx.x * blockDim.x + threadIdx.x;
    if (idx < B1_ELEMS) {
        int nn = idx / D_INP, i = idx % D_INP;
        int n = nn >> 1;
        float g = expf(gamma_log[n]);
        float v = g * (((nn & 1) == 0) ? Br[n * D_INP + i] : Bi[n * D_INP + i]);
        g_B1[idx] = __float2half_rn(v);
    } else if (idx < B1_ELEMS + W2_ELEMS) {
        int j = idx - B1_ELEMS;
        int o = j / KCAT, k = j % KCAT;
        float v;
        if (k < NBU) {
            int n = k >> 1;
            v = ((k & 1) == 0) ? 2.0f * Cr[o * N_ST + n] : -2.0f * Ci[o * N_ST + n];
        } else {
            v = Dm[o * D_INP + (k - NBU)];
        }
        g_W2[j] = __float2half_rn(v);
    }
}

__global__ void k_cvtU(const float* __restrict__ u) {
    int idx = blockIdx.x * blockDim.x + threadIdx.x;
    if (idx >= M_TOT * D_INP / 4) return;
    int m = idx / (D_INP / 4), i = (idx % (D_INP / 4)) * 4;
    float4 v = *(const float4*)(u + (size_t)m * D_INP + i);
    __half2 h0 = __floats2half2_rn(v.x, v.y);
    __half2 h1 = __floats2half2_rn(v.z, v.w);
    __half2* dst = (__half2*)(g_A2 + (size_t)m * KCAT + NBU + i);
    dst[0] = h0;
    dst[1] = h1;
}

// ---------------- GEMM mainloop: CTA tile 128(M) x 256(N), BK=32 ----------------
// 8 warps as 2(m) x 4(n); warp tile 64x64; mma.m16n8k16; acc[4][8][4].
#define BK       32
#define PADK     40                       // padded k-stride (elems)
#define TILE_A_B (128 * PADK * 2)         // 10240 B
#define TILE_B_B (256 * PADK * 2)         // 20480 B
#define STAGE_B  (TILE_A_B + TILE_B_B)    // 30720 B
#define STAGES   4
#define SMEM_GEMM (STAGES * STAGE_B)      // 122880 B

__device__ __forceinline__ void gemm_mainloop(
    uint32_t sb, const __half* A0, const __half* B0,
    int K, int lda, int ldb, float acc[4][8][4],
    int tid, int wm, int wn, int lid) {

    const int NC = K / BK;

    auto issue_load = [&](int c) {
        const int s = c % STAGES;
        const uint32_t stb = sb + s * STAGE_B;
        const int k0 = c * BK;
#pragma unroll
        for (int r = 0; r < 2; r++) {                // A: 512 chunks
            int idx = tid + r * 256;
            int row = idx >> 2, ch = idx & 3;
            uint32_t soff = (uint32_t)(row * (PADK * 2) + ch * 16);
            CP_ASYNC16(stb + soff, A0 + (size_t)row * lda + k0 + ch * 8);
        }
#pragma unroll
        for (int r = 0; r < 4; r++) {                // B: 1024 chunks
            int idx = tid + r * 256;
            int row = idx >> 2, ch = idx & 3;
            uint32_t soff = (uint32_t)(row * (PADK * 2) + ch * 16);
            CP_ASYNC16(stb + TILE_A_B + soff, B0 + (size_t)row * ldb + k0 + ch * 8);
        }
        CP_COMMIT();
    };

    const int aRow = lid & 15;
    const int aCol = (lid >> 4) << 3;
    const int bRow = (lid & 7) + ((lid >> 4) << 3);
    const int bCol = ((lid >> 3) & 1) << 3;

    issue_load(0);
    issue_load(1);
    issue_load(2);

    for (int c = 0; c < NC; c++) {
        CP_WAIT2();
        __syncthreads();
        if (c + 3 < NC) issue_load(c + 3);
        else            CP_COMMIT();

        const uint32_t stb = sb + (c % STAGES) * STAGE_B;
        const uint32_t sA = stb;
        const uint32_t sB = stb + TILE_A_B;

#pragma unroll
        for (int kk = 0; kk < BK; kk += 16) {
            uint32_t a[4][4], b[4][4];
#pragma unroll
            for (int mf = 0; mf < 4; mf++) {
                uint32_t ad = sA + (uint32_t)((wm * 64 + mf * 16 + aRow) * (PADK * 2) + (kk + aCol) * 2);
                LDSM4(a[mf][0], a[mf][1], a[mf][2], a[mf][3], ad);
            }
#pragma unroll
            for (int p = 0; p < 4; p++) {
                uint32_t bd = sB + (uint32_t)((wn * 64 + p * 16 + bRow) * (PADK * 2) + (kk + bCol) * 2);
                LDSM4(b[p][0], b[p][1], b[p][2], b[p][3], bd);
            }
#pragma unroll
            for (int mf = 0; mf < 4; mf++)
#pragma unroll
                for (int nf = 0; nf < 8; nf++)
                    MMA16816(acc[mf][nf], a[mf], b[nf >> 1][(nf & 1) * 2], b[nf >> 1][(nf & 1) * 2 + 1]);
        }
        __syncthreads();
    }
    CP_WAIT0();
}

// ---------------- GEMM1 + fused chunk-local scan ----------------
#define SCAN_STRIDE 264
#define SMEM_SCAN   (128 * SCAN_STRIDE * 4)   // 135168 B

__global__ __launch_bounds__(256, 1)
void gemm1_scan(const __half* __restrict__ A,
                const __half* __restrict__ B) {
    extern __shared__ char smem[];
    const uint32_t sb = smem_u32(smem);
    const int tid = threadIdx.x;
    const int wid = tid >> 5, lid = tid & 31;
    const int m0 = blockIdx.y * 128;
    const int n0 = blockIdx.x * 256;
    const int wm = wid >> 2, wn = wid & 3;

    float acc[4][8][4];
#pragma unroll
    for (int i = 0; i < 4; i++)
#pragma unroll
        for (int j = 0; j < 8; j++)
#pragma unroll
            for (int q = 0; q < 4; q++) acc[i][j][q] = 0.0f;

    gemm_mainloop(sb, A + (size_t)m0 * KCAT, B + (size_t)n0 * D_INP,
                  D_INP, KCAT, D_INP, acc, tid, wm, wn, lid);

    __syncthreads();            // pipeline smem dead, reuse for scan buffer

    float* sc = (float*)smem;   // [128][SCAN_STRIDE]
    const int gid = lid >> 2, tig = lid & 3;
#pragma unroll
    for (int mf = 0; mf < 4; mf++) {
        const int row = wm * 64 + mf * 16 + gid;
#pragma unroll
        for (int nf = 0; nf < 8; nf++) {
            const int col = wn * 64 + nf * 8 + tig * 2;
            *(float2*)(sc + row * SCAN_STRIDE + col) =
                make_float2(acc[mf][nf][0], acc[mf][nf][1]);
            *(float2*)(sc + (row + 8) * SCAN_STRIDE + col) =
                make_float2(acc[mf][nf][2], acc[mf][nf][3]);
        }
    }
    __syncthreads();

    // chunk-local complex scan: 128 complex pairs in this tile
    if (tid < 128) {
        const int np = (n0 >> 1) + tid;         // global state index
        const float2 lam = g_lam[np];
        const int b = m0 >> 12;                 // / T_LEN
        const int c = (m0 & (T_LEN - 1)) >> 7;  // / CHUNK
        float xr = 0.0f, xi = 0.0f;
        __half* out = g_A2 + (size_t)m0 * KCAT + 2 * np;
#pragma unroll 4
        for (int t = 0; t < CHUNK; t++) {
            float2 bu = *(const float2*)(sc + t * SCAN_STRIDE + 2 * tid);
            float nxr = fmaf(lam.x, xr, fmaf(-lam.y, xi, bu.x));
            float nxi = fmaf(lam.x, xi, fmaf(lam.y, xr, bu.y));
            xr = nxr; xi = nxi;
            *(__half2*)(out + (size_t)t * KCAT) = __floats2half2_rn(xr, xi);
        }
        g_F[(b * NCHUNK + c) * N_ST + np] = make_float2(xr, xi);
    }
}

// ---------------- GEMM2: y[M,256] = A2 @ W2^T, single n-tile ----------------
__global__ __launch_bounds__(256, 1)
void gemm2_out(const __half* __restrict__ A,
               const __half* __restrict__ B,
               float* __restrict__ C) {
    extern __shared__ char smem[];
    const uint32_t sb = smem_u32(smem);
    const int tid = threadIdx.x;
    const int wid = tid >> 5, lid = tid & 31;
    const int m0 = blockIdx.y * 128;
    const int wm = wid >> 2, wn = wid & 3;

    float acc[4][8][4];
#pragma unroll
    for (int i = 0; i < 4; i++)
#pragma unroll
        for (int j = 0; j < 8; j++)
#pragma unroll
            for (int q = 0; q < 4; q++) acc[i][j][q] = 0.0f;

    gemm_mainloop(sb, A + (size_t)m0 * KCAT, B,
                  KCAT, KCAT, KCAT, acc, tid, wm, wn, lid);

    const int gid = lid >> 2, tig = lid & 3;
#pragma unroll
    for (int mf = 0; mf < 4; mf++) {
        const int row = m0 + wm * 64 + mf * 16 + gid;
#pragma unroll
        for (int nf = 0; nf < 8; nf++) {
            const int col = wn * 64 + nf * 8 + tig * 2;
            *(float2*)(C + (size_t)row * D_OUTP + col) =
                make_float2(acc[mf][nf][0], acc[mf][nf][1]);
            *(float2*)(C + (size_t)(row + 8) * D_OUTP + col) =
                make_float2(acc[mf][nf][2], acc[mf][nf][3]);
        }
    }
}

// ---------------- chunk-level prefix over finals ----------------
__global__ void k_chunk_prefix() {
    int id = blockIdx.x * blockDim.x + threadIdx.x;
    if (id >= B_SZ * N_ST) return;
    int n = id & (N_ST - 1);
    int b = id >> 9;
    float2 lamL = g_lamL[n];
    float sr = 0.0f, si = 0.0f;
#pragma unroll
    for (int c = 0; c < NCHUNK; c++) {
        int idx = (b * NCHUNK + c) * N_ST + n;
        g_carry[idx] = make_float2(sr, si);
        float2 f = g_F[idx];
        float nsr = fmaf(lamL.x, sr, fmaf(-lamL.y, si, f.x));
        float nsi = fmaf(lamL.x, si, fmaf(lamL.y, sr, f.y));
        sr = nsr; si = nsi;
    }
}

// ---------------- carry correction: x_t += lam^{t+1} * carry ----------------
// Vectorized: each thread handles 2 adjacent complex states (one uint2 per t).
__global__ void k_correct() {
    int id = blockIdx.x * blockDim.x + threadIdx.x;
    if (id >= B_SZ * NCHUNK * (N_ST / 2)) return;
    int sp = id & (N_ST / 2 - 1);             // state pair 0..255
    int c = (id >> 8) & (NCHUNK - 1);
    int b = id >> 13;
    if (c == 0) return;                       // carry is zero for chunk 0
    const int np0 = 2 * sp, np1 = 2 * sp + 1;
    const int cbase = (b * NCHUNK + c) * N_ST;
    float2 ca = g_carry[cbase + np0];
    float2 cb = g_carry[cbase + np1];
    float2 la = g_lam[np0];
    float2 lb = g_lam[np1];
    float ar = ca.x, ai = ca.y;
    float br = cb.x, bi = cb.y;
    __half2* xp = (__half2*)(g_A2 + ((size_t)(b * T_LEN + c * CHUNK)) * KCAT + 4 * sp);
    const int stride2 = KCAT / 2;             // __half2 stride per t
#pragma unroll 4
    for (int t = 0; t < CHUNK; t++) {
        float nar = ar * la.x - ai * la.y;
        float nai = ar * la.y + ai * la.x;
        ar = nar; ai = nai;
        float nbr = br * lb.x - bi * lb.y;
        float nbi = br * lb.y + bi * lb.x;
        br = nbr; bi = nbi;
        uint2* up = (uint2*)(xp + (size_t)t * stride2);
        uint2 raw = *up;
        __half2 v0 = *(__half2*)&raw.x;
        __half2 v1 = *(__half2*)&raw.y;
        float2 x0 = __half22float2(v0);
        float2 x1 = __half22float2(v1);
        __half2 o0 = __floats2half2_rn(x0.x + ar, x0.y + ai);
        __half2 o1 = __floats2half2_rn(x1.x + br, x1.y + bi);
        uint2 out;
        out.x = *(uint32_t*)&o0;
        out.y = *(uint32_t*)&o1;
        *up = out;
    }
}

// ---------------- launch ----------------
extern "C" void kernel_launch(void* const* d_in, const int* in_sizes, int n_in,
                              void* d_out, int out_size) {
    const float* u_in      = (const float*)d_in[0];
    const float* nu_log    = (const float*)d_in[1];
    const float* theta_log = (const float*)d_in[2];
    const float* gamma_log = (const float*)d_in[3];
    const float* B_real    = (const float*)d_in[4];
    const float* B_imag    = (const float*)d_in[5];
    const float* C_real    = (const float*)d_in[6];
    const float* C_imag    = (const float*)d_in[7];
    const float* Dm        = (const float*)d_in[8];
    float* y = (float*)d_out;

    __half *a2, *b1, *w2;
    cudaGetSymbolAddress((void**)&a2, g_A2);
    cudaGetSymbolAddress((void**)&b1, g_B1);
    cudaGetSymbolAddress((void**)&w2, g_W2);

    cudaFuncSetAttribute(gemm1_scan,
                         cudaFuncAttributeMaxDynamicSharedMemorySize, SMEM_SCAN);
    cudaFuncSetAttribute(gemm2_out,
                         cudaFuncAttributeMaxDynamicSharedMemorySize, SMEM_GEMM);

    // setup / conversions
    k_setup<<<2, 256>>>(nu_log, theta_log);
    k_prepW<<<(B1_ELEMS + W2_ELEMS + 255) / 256, 256>>>(gamma_log, B_real, B_imag,
                                                        C_real, C_imag, Dm);
    k_cvtU<<<(M_TOT * D_INP / 4 + 255) / 256, 256>>>(u_in);

    // GEMM1 + chunk-local scan: writes X_local (fp16) into A2 and chunk finals
    {
        dim3 grid(NBU / 256, M_TOT / 128);
        gemm1_scan<<<grid, 256, SMEM_SCAN>>>(a2 + NBU, b1);
    }

    // chunk prefix + carry correction
    k_chunk_prefix<<<(B_SZ * N_ST + 255) / 256, 256>>>();
    k_correct<<<(B_SZ * NCHUNK * (N_ST / 2) + 255) / 256, 256>>>();

    // GEMM 2: y[M, 256] = [X | u] @ W2^T, K=1280, single n-tile
    {
        dim3 grid(1, M_TOT / 128);
        gemm2_out<<<grid, 256, SMEM_GEMM>>>(a2, w2, y);
    }
}

// round 10
// speedup vs baseline: 1.5101x; 1.0329x over previous
#include <cuda_runtime.h>
#include <cuda_fp16.h>
#include <cstdint>

// ---------------- problem constants ----------------
#define B_SZ   8
#define T_LEN  4096
#define D_INP  256
#define D_OUTP 256
#define N_ST   512
#define M_TOT  (B_SZ * T_LEN)      // 32768
#define NBU    (2 * N_ST)          // 1024
#define KCAT   (NBU + D_INP)       // 1280
#define CHUNK  128
#define NCHUNK (T_LEN / CHUNK)     // 32

// ---------------- device scratch ----------------
// A2 layout: cols [0,1024) = X interleaved (2n = xr_n, 2n+1 = xi_n), cols [1024,1280) = u
__device__ __half g_A2[(size_t)M_TOT * KCAT];
__device__ __half g_B1[NBU * D_INP];             // gamma-scaled B, interleaved rows
__device__ __half g_W2[D_OUTP * KCAT];           // K-interleaved [2Cr/-2Ci | D]
__device__ float2 g_lam [N_ST];
__device__ float2 g_lamL[N_ST];
__device__ float2 g_F    [B_SZ * NCHUNK * N_ST];
__device__ float2 g_carry[B_SZ * NCHUNK * N_ST];

// ---------------- helpers ----------------
__device__ __forceinline__ uint32_t smem_u32(const void* p) {
    uint32_t a;
    asm("{ .reg .u64 t; cvta.to.shared.u64 t, %1; cvt.u32.u64 %0, t; }" : "=r"(a) : "l"(p));
    return a;
}

#define CP_ASYNC16(dst, src) \
    asm volatile("cp.async.cg.shared.global [%0], [%1], 16;" :: "r"(dst), "l"(src))
#define CP_COMMIT() asm volatile("cp.async.commit_group;")
#define CP_WAIT2()  asm volatile("cp.async.wait_group 2;")
#define CP_WAIT0()  asm volatile("cp.async.wait_group 0;")

#define LDSM4(r0, r1, r2, r3, addr) \
    asm volatile("ldmatrix.sync.aligned.m8n8.x4.shared.b16 {%0,%1,%2,%3}, [%4];" \
        : "=r"(r0), "=r"(r1), "=r"(r2), "=r"(r3) : "r"(addr))

#define MMA16816(d, a, b0, b1) \
    asm volatile("mma.sync.aligned.m16n8k16.row.col.f32.f16.f16.f32 " \
        "{%0,%1,%2,%3}, {%4,%5,%6,%7}, {%8,%9}, {%0,%1,%2,%3};" \
        : "+f"(d[0]), "+f"(d[1]), "+f"(d[2]), "+f"(d[3]) \
        : "r"(a[0]), "r"(a[1]), "r"(a[2]), "r"(a[3]), "r"(b0), "r"(b1))

// ---------------- setup kernels ----------------
__global__ void k_setup(const float* __restrict__ nu_log,
                        const float* __restrict__ theta_log) {
    int n = blockIdx.x * blockDim.x + threadIdx.x;
    if (n >= N_ST) return;
    float lm = expf(-expf(nu_log[n]));
    float th = expf(theta_log[n]);
    float2 lam = make_float2(lm * cosf(th), lm * sinf(th));
    g_lam[n] = lam;
    float2 p = lam;
#pragma unroll
    for (int i = 0; i < 7; i++) {
        float2 q;
        q.x = p.x * p.x - p.y * p.y;
        q.y = 2.0f * p.x * p.y;
        p = q;
    }
    g_lamL[n] = p;
}

// merged weight prep:
//   idx < NBU*D_INP:         B1 (interleaved rows: 2n=gamma*Br, 2n+1=gamma*Bi)
//   else:                    W2 (K-interleaved [2Cr/-2Ci | D])
#define B1_ELEMS (NBU * D_INP)
#define W2_ELEMS (D_OUTP * KCAT)
__global__ void k_prepW(const float* __restrict__ gamma_log,
                        const float* __restrict__ Br,
                        const float* __restrict__ Bi,
                        const float* __restrict__ Cr,
                        const float* __restrict__ Ci,
                        const float* __restrict__ Dm) {
    int idx = blockIdx.x * blockDim.x + threadIdx.x;
    if (idx < B1_ELEMS) {
        int nn = idx / D_INP, i = idx % D_INP;
        int n = nn >> 1;
        float g = expf(gamma_log[n]);
        float v = g * (((nn & 1) == 0) ? Br[n * D_INP + i] : Bi[n * D_INP + i]);
        g_B1[idx] = __float2half_rn(v);
    } else if (idx < B1_ELEMS + W2_ELEMS) {
        int j = idx - B1_ELEMS;
        int o = j / KCAT, k = j % KCAT;
        float v;
        if (k < NBU) {
            int n = k >> 1;
            v = ((k & 1) == 0) ? 2.0f * Cr[o * N_ST + n] : -2.0f * Ci[o * N_ST + n];
        } else {
            v = Dm[o * D_INP + (k - NBU)];
        }
        g_W2[j] = __float2half_rn(v);
    }
}

__global__ void k_cvtU(const float* __restrict__ u) {
    int idx = blockIdx.x * blockDim.x + threadIdx.x;
    if (idx >= M_TOT * D_INP / 4) return;
    int m = idx / (D_INP / 4), i = (idx % (D_INP / 4)) * 4;
    float4 v = *(const float4*)(u + (size_t)m * D_INP + i);
    __half2 h0 = __floats2half2_rn(v.x, v.y);
    __half2 h1 = __floats2half2_rn(v.z, v.w);
    __half2* dst = (__half2*)(g_A2 + (size_t)m * KCAT + NBU + i);
    dst[0] = h0;
    dst[1] = h1;
}

// ---------------- GEMM mainloop: CTA tile 128(M) x 256(N), BK=32 ----------------
// 8 warps as 2(m) x 4(n); warp tile 64x64; mma.m16n8k16; acc[4][8][4].
// Fragments are register double-buffered: LDSM(kk0) -> cp.async issue ->
// LDSM(kk16) -> MMA(kk0) -> MMA(kk16), hiding ldmatrix latency.
#define BK       32
#define PADK     40                       // padded k-stride (elems)
#define TILE_A_B (128 * PADK * 2)         // 10240 B
#define TILE_B_B (256 * PADK * 2)         // 20480 B
#define STAGE_B  (TILE_A_B + TILE_B_B)    // 30720 B
#define STAGES   4
#define SMEM_GEMM (STAGES * STAGE_B)      // 122880 B

__device__ __forceinline__ void gemm_mainloop(
    uint32_t sb, const __half* A0, const __half* B0,
    int K, int lda, int ldb, float acc[4][8][4],
    int tid, int wm, int wn, int lid) {

    const int NC = K / BK;

    auto issue_load = [&](int c) {
        const int s = c % STAGES;
        const uint32_t stb = sb + s * STAGE_B;
        const int k0 = c * BK;
#pragma unroll
        for (int r = 0; r < 2; r++) {                // A: 512 chunks
            int idx = tid + r * 256;
            int row = idx >> 2, ch = idx & 3;
            uint32_t soff = (uint32_t)(row * (PADK * 2) + ch * 16);
            CP_ASYNC16(stb + soff, A0 + (size_t)row * lda + k0 + ch * 8);
        }
#pragma unroll
        for (int r = 0; r < 4; r++) {                // B: 1024 chunks
            int idx = tid + r * 256;
            int row = idx >> 2, ch = idx & 3;
            uint32_t soff = (uint32_t)(row * (PADK * 2) + ch * 16);
            CP_ASYNC16(stb + TILE_A_B + soff, B0 + (size_t)row * ldb + k0 + ch * 8);
        }
        CP_COMMIT();
    };

    const int aRow = lid & 15;
    const int aCol = (lid >> 4) << 3;
    const int bRow = (lid & 7) + ((lid >> 4) << 3);
    const int bCol = ((lid >> 3) & 1) << 3;

    issue_load(0);
    issue_load(1);
    issue_load(2);

    uint32_t a[2][4][4], b[2][4][4];

    for (int c = 0; c < NC; c++) {
        CP_WAIT2();
        __syncthreads();

        const uint32_t stb = sb + (c % STAGES) * STAGE_B;
        const uint32_t sA = stb;
        const uint32_t sB = stb + TILE_A_B;

        // LDSM frags for kk=0
#pragma unroll
        for (int mf = 0; mf < 4; mf++) {
            uint32_t ad = sA + (uint32_t)((wm * 64 + mf * 16 + aRow) * (PADK * 2) + aCol * 2);
            LDSM4(a[0][mf][0], a[0][mf][1], a[0][mf][2], a[0][mf][3], ad);
        }
#pragma unroll
        for (int p = 0; p < 4; p++) {
            uint32_t bd = sB + (uint32_t)((wn * 64 + p * 16 + bRow) * (PADK * 2) + bCol * 2);
            LDSM4(b[0][p][0], b[0][p][1], b[0][p][2], b[0][p][3], bd);
        }

        // issue next stage's async loads (covers kk0 LDSM latency)
        if (c + 3 < NC) issue_load(c + 3);
        else            CP_COMMIT();

        // LDSM frags for kk=16 (latency covered by kk0 MMAs below)
#pragma unroll
        for (int mf = 0; mf < 4; mf++) {
            uint32_t ad = sA + (uint32_t)((wm * 64 + mf * 16 + aRow) * (PADK * 2) + (16 + aCol) * 2);
            LDSM4(a[1][mf][0], a[1][mf][1], a[1][mf][2], a[1][mf][3], ad);
        }
#pragma unroll
        for (int p = 0; p < 4; p++) {
            uint32_t bd = sB + (uint32_t)((wn * 64 + p * 16 + bRow) * (PADK * 2) + (16 + bCol) * 2);
            LDSM4(b[1][p][0], b[1][p][1], b[1][p][2], b[1][p][3], bd);
        }

        // MMAs kk=0
#pragma unroll
        for (int mf = 0; mf < 4; mf++)
#pragma unroll
            for (int nf = 0; nf < 8; nf++)
                MMA16816(acc[mf][nf], a[0][mf], b[0][nf >> 1][(nf & 1) * 2], b[0][nf >> 1][(nf & 1) * 2 + 1]);
        // MMAs kk=16
#pragma unroll
        for (int mf = 0; mf < 4; mf++)
#pragma unroll
            for (int nf = 0; nf < 8; nf++)
                MMA16816(acc[mf][nf], a[1][mf], b[1][nf >> 1][(nf & 1) * 2], b[1][nf >> 1][(nf & 1) * 2 + 1]);

        __syncthreads();
    }
    CP_WAIT0();
}

// ---------------- GEMM1 + fused chunk-local scan ----------------
#define SCAN_STRIDE 264
#define SMEM_SCAN   (128 * SCAN_STRIDE * 4)   // 135168 B

__global__ __launch_bounds__(256, 1)
void gemm1_scan(const __half* __restrict__ A,
                const __half* __restrict__ B) {
    extern __shared__ char smem[];
    const uint32_t sb = smem_u32(smem);
    const int tid = threadIdx.x;
    const int wid = tid >> 5, lid = tid & 31;
    const int m0 = blockIdx.y * 128;
    const int n0 = blockIdx.x * 256;
    const int wm = wid >> 2, wn = wid & 3;

    float acc[4][8][4];
#pragma unroll
    for (int i = 0; i < 4; i++)
#pragma unroll
        for (int j = 0; j < 8; j++)
#pragma unroll
            for (int q = 0; q < 4; q++) acc[i][j][q] = 0.0f;

    gemm_mainloop(sb, A + (size_t)m0 * KCAT, B + (size_t)n0 * D_INP,
                  D_INP, KCAT, D_INP, acc, tid, wm, wn, lid);

    __syncthreads();            // pipeline smem dead, reuse for scan buffer

    float* sc = (float*)smem;   // [128][SCAN_STRIDE]
    const int gid = lid >> 2, tig = lid & 3;
#pragma unroll
    for (int mf = 0; mf < 4; mf++) {
        const int row = wm * 64 + mf * 16 + gid;
#pragma unroll
        for (int nf = 0; nf < 8; nf++) {
            const int col = wn * 64 + nf * 8 + tig * 2;
            *(float2*)(sc + row * SCAN_STRIDE + col) =
                make_float2(acc[mf][nf][0], acc[mf][nf][1]);
            *(float2*)(sc + (row + 8) * SCAN_STRIDE + col) =
                make_float2(acc[mf][nf][2], acc[mf][nf][3]);
        }
    }
    __syncthreads();

    // chunk-local complex scan: 128 complex pairs in this tile
    if (tid < 128) {
        const int np = (n0 >> 1) + tid;         // global state index
        const float2 lam = g_lam[np];
        const int b = m0 >> 12;                 // / T_LEN
        const int c = (m0 & (T_LEN - 1)) >> 7;  // / CHUNK
        float xr = 0.0f, xi = 0.0f;
        __half* out = g_A2 + (size_t)m0 * KCAT + 2 * np;
#pragma unroll 4
        for (int t = 0; t < CHUNK; t++) {
            float2 bu = *(const float2*)(sc + t * SCAN_STRIDE + 2 * tid);
            float nxr = fmaf(lam.x, xr, fmaf(-lam.y, xi, bu.x));
            float nxi = fmaf(lam.x, xi, fmaf(lam.y, xr, bu.y));
            xr = nxr; xi = nxi;
            *(__half2*)(out + (size_t)t * KCAT) = __floats2half2_rn(xr, xi);
        }
        g_F[(b * NCHUNK + c) * N_ST + np] = make_float2(xr, xi);
    }
}

// ---------------- GEMM2: y[M,256] = A2 @ W2^T, single n-tile ----------------
__global__ __launch_bounds__(256, 1)
void gemm2_out(const __half* __restrict__ A,
               const __half* __restrict__ B,
               float* __restrict__ C) {
    extern __shared__ char smem[];
    const uint32_t sb = smem_u32(smem);
    const int tid = threadIdx.x;
    const int wid = tid >> 5, lid = tid & 31;
    const int m0 = blockIdx.y * 128;
    const int wm = wid >> 2, wn = wid & 3;

    float acc[4][8][4];
#pragma unroll
    for (int i = 0; i < 4; i++)
#pragma unroll
        for (int j = 0; j < 8; j++)
#pragma unroll
            for (int q = 0; q < 4; q++) acc[i][j][q] = 0.0f;

    gemm_mainloop(sb, A + (size_t)m0 * KCAT, B,
                  KCAT, KCAT, KCAT, acc, tid, wm, wn, lid);

    const int gid = lid >> 2, tig = lid & 3;
#pragma unroll
    for (int mf = 0; mf < 4; mf++) {
        const int row = m0 + wm * 64 + mf * 16 + gid;
#pragma unroll
        for (int nf = 0; nf < 8; nf++) {
            const int col = wn * 64 + nf * 8 + tig * 2;
            *(float2*)(C + (size_t)row * D_OUTP + col) =
                make_float2(acc[mf][nf][0], acc[mf][nf][1]);
            *(float2*)(C + (size_t)(row + 8) * D_OUTP + col) =
                make_float2(acc[mf][nf][2], acc[mf][nf][3]);
        }
    }
}

// ---------------- chunk-level prefix over finals ----------------
__global__ void k_chunk_prefix() {
    int id = blockIdx.x * blockDim.x + threadIdx.x;
    if (id >= B_SZ * N_ST) return;
    int n = id & (N_ST - 1);
    int b = id >> 9;
    float2 lamL = g_lamL[n];
    float sr = 0.0f, si = 0.0f;
#pragma unroll
    for (int c = 0; c < NCHUNK; c++) {
        int idx = (b * NCHUNK + c) * N_ST + n;
        g_carry[idx] = make_float2(sr, si);
        float2 f = g_F[idx];
        float nsr = fmaf(lamL.x, sr, fmaf(-lamL.y, si, f.x));
        float nsi = fmaf(lamL.x, si, fmaf(lamL.y, sr, f.y));
        sr = nsr; si = nsi;
    }
}

// ---------------- carry correction: x_t += lam^{t+1} * carry ----------------
// Vectorized: each thread handles 2 adjacent complex states (one uint2 per t).
__global__ void k_correct() {
    int id = blockIdx.x * blockDim.x + threadIdx.x;
    if (id >= B_SZ * NCHUNK * (N_ST / 2)) return;
    int sp = id & (N_ST / 2 - 1);             // state pair 0..255
    int c = (id >> 8) & (NCHUNK - 1);
    int b = id >> 13;
    if (c == 0) return;                       // carry is zero for chunk 0
    const int np0 = 2 * sp, np1 = 2 * sp + 1;
    const int cbase = (b * NCHUNK + c) * N_ST;
    float2 ca = g_carry[cbase + np0];
    float2 cb = g_carry[cbase + np1];
    float2 la = g_lam[np0];
    float2 lb = g_lam[np1];
    float ar = ca.x, ai = ca.y;
    float br = cb.x, bi = cb.y;
    __half2* xp = (__half2*)(g_A2 + ((size_t)(b * T_LEN + c * CHUNK)) * KCAT + 4 * sp);
    const int stride2 = KCAT / 2;             // __half2 stride per t
#pragma unroll 4
    for (int t = 0; t < CHUNK; t++) {
        float nar = ar * la.x - ai * la.y;
        float nai = ar * la.y + ai * la.x;
        ar = nar; ai = nai;
        float nbr = br * lb.x - bi * lb.y;
        float nbi = br * lb.y + bi * lb.x;
        br = nbr; bi = nbi;
        uint2* up = (uint2*)(xp + (size_t)t * stride2);
        uint2 raw = *up;
        __half2 v0 = *(__half2*)&raw.x;
        __half2 v1 = *(__half2*)&raw.y;
        float2 x0 = __half22float2(v0);
        float2 x1 = __half22float2(v1);
        __half2 o0 = __floats2half2_rn(x0.x + ar, x0.y + ai);
        __half2 o1 = __floats2half2_rn(x1.x + br, x1.y + bi);
        uint2 out;
        out.x = *(uint32_t*)&o0;
        out.y = *(uint32_t*)&o1;
        *up = out;
    }
}

// ---------------- launch ----------------
extern "C" void kernel_launch(void* const* d_in, const int* in_sizes, int n_in,
                              void* d_out, int out_size) {
    const float* u_in      = (const float*)d_in[0];
    const float* nu_log    = (const float*)d_in[1];
    const float* theta_log = (const float*)d_in[2];
    const float* gamma_log = (const float*)d_in[3];
    const float* B_real    = (const float*)d_in[4];
    const float* B_imag    = (const float*)d_in[5];
    const float* C_real    = (const float*)d_in[6];
    const float* C_imag    = (const float*)d_in[7];
    const float* Dm        = (const float*)d_in[8];
    float* y = (float*)d_out;

    __half *a2, *b1, *w2;
    cudaGetSymbolAddress((void**)&a2, g_A2);
    cudaGetSymbolAddress((void**)&b1, g_B1);
    cudaGetSymbolAddress((void**)&w2, g_W2);

    cudaFuncSetAttribute(gemm1_scan,
                         cudaFuncAttributeMaxDynamicSharedMemorySize, SMEM_SCAN);
    cudaFuncSetAttribute(gemm2_out,
                         cudaFuncAttributeMaxDynamicSharedMemorySize, SMEM_GEMM);

    // setup / conversions
    k_setup<<<2, 256>>>(nu_log, theta_log);
    k_prepW<<<(B1_ELEMS + W2_ELEMS + 255) / 256, 256>>>(gamma_log, B_real, B_imag,
                                                        C_real, C_imag, Dm);
    k_cvtU<<<(M_TOT * D_INP / 4 + 255) / 256, 256>>>(u_in);

    // GEMM1 + chunk-local scan: writes X_local (fp16) into A2 and chunk finals
    {
        dim3 grid(NBU / 256, M_TOT / 128);
        gemm1_scan<<<grid, 256, SMEM_SCAN>>>(a2 + NBU, b1);
    }

    // chunk prefix + carry correction
    k_chunk_prefix<<<(B_SZ * N_ST + 255) / 256, 256>>>();
    k_correct<<<(B_SZ * NCHUNK * (N_ST / 2) + 255) / 256, 256>>>();

    // GEMM 2: y[M, 256] = [X | u] @ W2^T, K=1280, single n-tile
    {
        dim3 grid(1, M_TOT / 128);
        gemm2_out<<<grid, 256, SMEM_GEMM>>>(a2, w2, y);
    }
}

// round 11
// speedup vs baseline: 1.5453x; 1.0233x over previous
#include <cuda_runtime.h>
#include <cuda_fp16.h>
#include <cstdint>

// ---------------- problem constants ----------------
#define B_SZ   8
#define T_LEN  4096
#define D_INP  256
#define D_OUTP 256
#define N_ST   512
#define M_TOT  (B_SZ * T_LEN)      // 32768
#define NBU    (2 * N_ST)          // 1024
#define KCAT   (NBU + D_INP)       // 1280
#define CHUNK  128
#define NCHUNK (T_LEN / CHUNK)     // 32

// ---------------- device scratch ----------------
// A2 layout: cols [0,1024) = X interleaved (2n = xr_n, 2n+1 = xi_n), cols [1024,1280) = u
__device__ __half g_A2[(size_t)M_TOT * KCAT];
__device__ __half g_B1[NBU * D_INP];             // gamma-scaled B, interleaved rows
__device__ __half g_W2[D_OUTP * KCAT];           // K-interleaved [2Cr/-2Ci | D]
__device__ float2 g_lam [N_ST];
__device__ float2 g_lamL[N_ST];
__device__ float2 g_F    [B_SZ * NCHUNK * N_ST];
__device__ float2 g_carry[B_SZ * NCHUNK * N_ST];

// ---------------- helpers ----------------
__device__ __forceinline__ uint32_t smem_u32(const void* p) {
    uint32_t a;
    asm("{ .reg .u64 t; cvta.to.shared.u64 t, %1; cvt.u32.u64 %0, t; }" : "=r"(a) : "l"(p));
    return a;
}

#define CP_ASYNC16(dst, src) \
    asm volatile("cp.async.cg.shared.global [%0], [%1], 16;" :: "r"(dst), "l"(src))
#define CP_COMMIT() asm volatile("cp.async.commit_group;")
#define CP_WAIT2()  asm volatile("cp.async.wait_group 2;")
#define CP_WAIT0()  asm volatile("cp.async.wait_group 0;")

#define LDSM4(r0, r1, r2, r3, addr) \
    asm volatile("ldmatrix.sync.aligned.m8n8.x4.shared.b16 {%0,%1,%2,%3}, [%4];" \
        : "=r"(r0), "=r"(r1), "=r"(r2), "=r"(r3) : "r"(addr))

#define MMA16816(d, a, b0, b1) \
    asm volatile("mma.sync.aligned.m16n8k16.row.col.f32.f16.f16.f32 " \
        "{%0,%1,%2,%3}, {%4,%5,%6,%7}, {%8,%9}, {%0,%1,%2,%3};" \
        : "+f"(d[0]), "+f"(d[1]), "+f"(d[2]), "+f"(d[3]) \
        : "r"(a[0]), "r"(a[1]), "r"(a[2]), "r"(a[3]), "r"(b0), "r"(b1))

// ---------------- setup kernels ----------------
__global__ void k_setup(const float* __restrict__ nu_log,
                        const float* __restrict__ theta_log) {
    int n = blockIdx.x * blockDim.x + threadIdx.x;
    if (n >= N_ST) return;
    float lm = expf(-expf(nu_log[n]));
    float th = expf(theta_log[n]);
    float2 lam = make_float2(lm * cosf(th), lm * sinf(th));
    g_lam[n] = lam;
    float2 p = lam;
#pragma unroll
    for (int i = 0; i < 7; i++) {
        float2 q;
        q.x = p.x * p.x - p.y * p.y;
        q.y = 2.0f * p.x * p.y;
        p = q;
    }
    g_lamL[n] = p;
}

// merged weight prep
#define B1_ELEMS (NBU * D_INP)
#define W2_ELEMS (D_OUTP * KCAT)
__global__ void k_prepW(const float* __restrict__ gamma_log,
                        const float* __restrict__ Br,
                        const float* __restrict__ Bi,
                        const float* __restrict__ Cr,
                        const float* __restrict__ Ci,
                        const float* __restrict__ Dm) {
    int idx = blockIdx.x * blockDim.x + threadIdx.x;
    if (idx < B1_ELEMS) {
        int nn = idx / D_INP, i = idx % D_INP;
        int n = nn >> 1;
        float g = expf(gamma_log[n]);
        float v = g * (((nn & 1) == 0) ? Br[n * D_INP + i] : Bi[n * D_INP + i]);
        g_B1[idx] = __float2half_rn(v);
    } else if (idx < B1_ELEMS + W2_ELEMS) {
        int j = idx - B1_ELEMS;
        int o = j / KCAT, k = j % KCAT;
        float v;
        if (k < NBU) {
            int n = k >> 1;
            v = ((k & 1) == 0) ? 2.0f * Cr[o * N_ST + n] : -2.0f * Ci[o * N_ST + n];
        } else {
            v = Dm[o * D_INP + (k - NBU)];
        }
        g_W2[j] = __float2half_rn(v);
    }
}

__global__ void k_cvtU(const float* __restrict__ u) {
    int idx = blockIdx.x * blockDim.x + threadIdx.x;
    if (idx >= M_TOT * D_INP / 4) return;
    int m = idx / (D_INP / 4), i = (idx % (D_INP / 4)) * 4;
    float4 v = *(const float4*)(u + (size_t)m * D_INP + i);
    __half2 h0 = __floats2half2_rn(v.x, v.y);
    __half2 h1 = __floats2half2_rn(v.z, v.w);
    __half2* dst = (__half2*)(g_A2 + (size_t)m * KCAT + NBU + i);
    dst[0] = h0;
    dst[1] = h1;
}

// ---------------- GEMM mainloop: CTA 128(M) x 256(N), BK=32, 512 threads ----------------
// 16 warps as 2(m) x 8(n); warp tile 64x32; mma.m16n8k16; acc[4][4][4] (64 regs).
#define NTHREADS 512
#define BK       32
#define PADK     40                       // padded k-stride (elems)
#define TILE_A_B (128 * PADK * 2)         // 10240 B
#define TILE_B_B (256 * PADK * 2)         // 20480 B
#define STAGE_B  (TILE_A_B + TILE_B_B)    // 30720 B
#define STAGES   4
#define SMEM_GEMM (STAGES * STAGE_B)      // 122880 B

__device__ __forceinline__ void gemm_mainloop(
    uint32_t sb, const __half* A0, const __half* B0,
    int K, int lda, int ldb, float acc[4][4][4],
    int tid, int wm, int wn, int lid) {

    const int NC = K / BK;

    auto issue_load = [&](int c) {
        const int s = c % STAGES;
        const uint32_t stb = sb + s * STAGE_B;
        const int k0 = c * BK;
        {   // A: 512 chunks, one iter
            int row = tid >> 2, ch = tid & 3;
            uint32_t soff = (uint32_t)(row * (PADK * 2) + ch * 16);
            CP_ASYNC16(stb + soff, A0 + (size_t)row * lda + k0 + ch * 8);
        }
#pragma unroll
        for (int r = 0; r < 2; r++) {       // B: 1024 chunks
            int idx = tid + r * NTHREADS;
            int row = idx >> 2, ch = idx & 3;
            uint32_t soff = (uint32_t)(row * (PADK * 2) + ch * 16);
            CP_ASYNC16(stb + TILE_A_B + soff, B0 + (size_t)row * ldb + k0 + ch * 8);
        }
        CP_COMMIT();
    };

    const int aRow = lid & 15;
    const int aCol = (lid >> 4) << 3;
    const int bRow = (lid & 7) + ((lid >> 4) << 3);
    const int bCol = ((lid >> 3) & 1) << 3;

    issue_load(0);
    issue_load(1);
    issue_load(2);

    for (int c = 0; c < NC; c++) {
        CP_WAIT2();
        __syncthreads();
        if (c + 3 < NC) issue_load(c + 3);
        else            CP_COMMIT();

        const uint32_t stb = sb + (c % STAGES) * STAGE_B;
        const uint32_t sA = stb;
        const uint32_t sB = stb + TILE_A_B;

#pragma unroll
        for (int kk = 0; kk < BK; kk += 16) {
            uint32_t a[4][4], b[2][4];
#pragma unroll
            for (int mf = 0; mf < 4; mf++) {
                uint32_t ad = sA + (uint32_t)((wm * 64 + mf * 16 + aRow) * (PADK * 2) + (kk + aCol) * 2);
                LDSM4(a[mf][0], a[mf][1], a[mf][2], a[mf][3], ad);
            }
#pragma unroll
            for (int p = 0; p < 2; p++) {
                uint32_t bd = sB + (uint32_t)((wn * 32 + p * 16 + bRow) * (PADK * 2) + (kk + bCol) * 2);
                LDSM4(b[p][0], b[p][1], b[p][2], b[p][3], bd);
            }
#pragma unroll
            for (int mf = 0; mf < 4; mf++)
#pragma unroll
                for (int nf = 0; nf < 4; nf++)
                    MMA16816(acc[mf][nf], a[mf], b[nf >> 1][(nf & 1) * 2], b[nf >> 1][(nf & 1) * 2 + 1]);
        }
        __syncthreads();
    }
    CP_WAIT0();
}

// ---------------- GEMM1 + fused chunk-local scan ----------------
#define SCAN_STRIDE 264
#define SMEM_SCAN   (128 * SCAN_STRIDE * 4)   // 135168 B

__global__ __launch_bounds__(NTHREADS, 1)
void gemm1_scan(const __half* __restrict__ A,
                const __half* __restrict__ B) {
    extern __shared__ char smem[];
    const uint32_t sb = smem_u32(smem);
    const int tid = threadIdx.x;
    const int wid = tid >> 5, lid = tid & 31;
    const int m0 = blockIdx.y * 128;
    const int n0 = blockIdx.x * 256;
    const int wm = wid >> 3, wn = wid & 7;

    float acc[4][4][4];
#pragma unroll
    for (int i = 0; i < 4; i++)
#pragma unroll
        for (int j = 0; j < 4; j++)
#pragma unroll
            for (int q = 0; q < 4; q++) acc[i][j][q] = 0.0f;

    gemm_mainloop(sb, A + (size_t)m0 * KCAT, B + (size_t)n0 * D_INP,
                  D_INP, KCAT, D_INP, acc, tid, wm, wn, lid);

    __syncthreads();            // pipeline smem dead, reuse for scan buffer

    float* sc = (float*)smem;   // [128][SCAN_STRIDE]
    const int gid = lid >> 2, tig = lid & 3;
#pragma unroll
    for (int mf = 0; mf < 4; mf++) {
        const int row = wm * 64 + mf * 16 + gid;
#pragma unroll
        for (int nf = 0; nf < 4; nf++) {
            const int col = wn * 32 + nf * 8 + tig * 2;
            *(float2*)(sc + row * SCAN_STRIDE + col) =
                make_float2(acc[mf][nf][0], acc[mf][nf][1]);
            *(float2*)(sc + (row + 8) * SCAN_STRIDE + col) =
                make_float2(acc[mf][nf][2], acc[mf][nf][3]);
        }
    }
    __syncthreads();

    // chunk-local complex scan: 128 complex pairs in this tile
    if (tid < 128) {
        const int np = (n0 >> 1) + tid;         // global state index
        const float2 lam = g_lam[np];
        const int b = m0 >> 12;                 // / T_LEN
        const int c = (m0 & (T_LEN - 1)) >> 7;  // / CHUNK
        float xr = 0.0f, xi = 0.0f;
        __half* out = g_A2 + (size_t)m0 * KCAT + 2 * np;
#pragma unroll 4
        for (int t = 0; t < CHUNK; t++) {
            float2 bu = *(const float2*)(sc + t * SCAN_STRIDE + 2 * tid);
            float nxr = fmaf(lam.x, xr, fmaf(-lam.y, xi, bu.x));
            float nxi = fmaf(lam.x, xi, fmaf(lam.y, xr, bu.y));
            xr = nxr; xi = nxi;
            *(__half2*)(out + (size_t)t * KCAT) = __floats2half2_rn(xr, xi);
        }
        g_F[(b * NCHUNK + c) * N_ST + np] = make_float2(xr, xi);
    }
}

// ---------------- GEMM2: y[M,256] = A2 @ W2^T, single n-tile ----------------
__global__ __launch_bounds__(NTHREADS, 1)
void gemm2_out(const __half* __restrict__ A,
               const __half* __restrict__ B,
               float* __restrict__ C) {
    extern __shared__ char smem[];
    const uint32_t sb = smem_u32(smem);
    const int tid = threadIdx.x;
    const int wid = tid >> 5, lid = tid & 31;
    const int m0 = blockIdx.y * 128;
    const int wm = wid >> 3, wn = wid & 7;

    float acc[4][4][4];
#pragma unroll
    for (int i = 0; i < 4; i++)
#pragma unroll
        for (int j = 0; j < 4; j++)
#pragma unroll
            for (int q = 0; q < 4; q++) acc[i][j][q] = 0.0f;

    gemm_mainloop(sb, A + (size_t)m0 * KCAT, B,
                  KCAT, KCAT, KCAT, acc, tid, wm, wn, lid);

    const int gid = lid >> 2, tig = lid & 3;
#pragma unroll
    for (int mf = 0; mf < 4; mf++) {
        const int row = m0 + wm * 64 + mf * 16 + gid;
#pragma unroll
        for (int nf = 0; nf < 4; nf++) {
            const int col = wn * 32 + nf * 8 + tig * 2;
            *(float2*)(C + (size_t)row * D_OUTP + col) =
                make_float2(acc[mf][nf][0], acc[mf][nf][1]);
            *(float2*)(C + (size_t)(row + 8) * D_OUTP + col) =
                make_float2(acc[mf][nf][2], acc[mf][nf][3]);
        }
    }
}

// ---------------- chunk-level prefix over finals ----------------
__global__ void k_chunk_prefix() {
    int id = blockIdx.x * blockDim.x + threadIdx.x;
    if (id >= B_SZ * N_ST) return;
    int n = id & (N_ST - 1);
    int b = id >> 9;
    float2 lamL = g_lamL[n];
    float sr = 0.0f, si = 0.0f;
#pragma unroll
    for (int c = 0; c < NCHUNK; c++) {
        int idx = (b * NCHUNK + c) * N_ST + n;
        g_carry[idx] = make_float2(sr, si);
        float2 f = g_F[idx];
        float nsr = fmaf(lamL.x, sr, fmaf(-lamL.y, si, f.x));
        float nsi = fmaf(lamL.x, si, fmaf(lamL.y, sr, f.y));
        sr = nsr; si = nsi;
    }
}

// ---------------- carry correction: x_t += lam^{t+1} * carry ----------------
__global__ void k_correct() {
    int id = blockIdx.x * blockDim.x + threadIdx.x;
    if (id >= B_SZ * NCHUNK * (N_ST / 2)) return;
    int sp = id & (N_ST / 2 - 1);             // state pair 0..255
    int c = (id >> 8) & (NCHUNK - 1);
    int b = id >> 13;
    if (c == 0) return;                       // carry is zero for chunk 0
    const int np0 = 2 * sp, np1 = 2 * sp + 1;
    const int cbase = (b * NCHUNK + c) * N_ST;
    float2 ca = g_carry[cbase + np0];
    float2 cb = g_carry[cbase + np1];
    float2 la = g_lam[np0];
    float2 lb = g_lam[np1];
    float ar = ca.x, ai = ca.y;
    float br = cb.x, bi = cb.y;
    __half2* xp = (__half2*)(g_A2 + ((size_t)(b * T_LEN + c * CHUNK)) * KCAT + 4 * sp);
    const int stride2 = KCAT / 2;             // __half2 stride per t
#pragma unroll 4
    for (int t = 0; t < CHUNK; t++) {
        float nar = ar * la.x - ai * la.y;
        float nai = ar * la.y + ai * la.x;
        ar = nar; ai = nai;
        float nbr = br * lb.x - bi * lb.y;
        float nbi = br * lb.y + bi * lb.x;
        br = nbr; bi = nbi;
        uint2* up = (uint2*)(xp + (size_t)t * stride2);
        uint2 raw = *up;
        __half2 v0 = *(__half2*)&raw.x;
        __half2 v1 = *(__half2*)&raw.y;
        float2 x0 = __half22float2(v0);
        float2 x1 = __half22float2(v1);
        __half2 o0 = __floats2half2_rn(x0.x + ar, x0.y + ai);
        __half2 o1 = __floats2half2_rn(x1.x + br, x1.y + bi);
        uint2 out;
        out.x = *(uint32_t*)&o0;
        out.y = *(uint32_t*)&o1;
        *up = out;
    }
}

// ---------------- launch ----------------
extern "C" void kernel_launch(void* const* d_in, const int* in_sizes, int n_in,
                              void* d_out, int out_size) {
    const float* u_in      = (const float*)d_in[0];
    const float* nu_log    = (const float*)d_in[1];
    const float* theta_log = (const float*)d_in[2];
    const float* gamma_log = (const float*)d_in[3];
    const float* B_real    = (const float*)d_in[4];
    const float* B_imag    = (const float*)d_in[5];
    const float* C_real    = (const float*)d_in[6];
    const float* C_imag    = (const float*)d_in[7];
    const float* Dm        = (const float*)d_in[8];
    float* y = (float*)d_out;

    __half *a2, *b1, *w2;
    cudaGetSymbolAddress((void**)&a2, g_A2);
    cudaGetSymbolAddress((void**)&b1, g_B1);
    cudaGetSymbolAddress((void**)&w2, g_W2);

    cudaFuncSetAttribute(gemm1_scan,
                         cudaFuncAttributeMaxDynamicSharedMemorySize, SMEM_SCAN);
    cudaFuncSetAttribute(gemm2_out,
                         cudaFuncAttributeMaxDynamicSharedMemorySize, SMEM_GEMM);

    // setup / conversions
    k_setup<<<2, 256>>>(nu_log, theta_log);
    k_prepW<<<(B1_ELEMS + W2_ELEMS + 255) / 256, 256>>>(gamma_log, B_real, B_imag,
                                                        C_real, C_imag, Dm);
    k_cvtU<<<(M_TOT * D_INP / 4 + 255) / 256, 256>>>(u_in);

    // GEMM1 + chunk-local scan: writes X_local (fp16) into A2 and chunk finals
    {
        dim3 grid(NBU / 256, M_TOT / 128);
        gemm1_scan<<<grid, NTHREADS, SMEM_SCAN>>>(a2 + NBU, b1);
    }

    // chunk prefix + carry correction
    k_chunk_prefix<<<(B_SZ * N_ST + 255) / 256, 256>>>();
    k_correct<<<(B_SZ * NCHUNK * (N_ST / 2) + 255) / 256, 256>>>();

    // GEMM 2: y[M, 256] = [X | u] @ W2^T, K=1280, single n-tile
    {
        dim3 grid(1, M_TOT / 128);
        gemm2_out<<<grid, NTHREADS, SMEM_GEMM>>>(a2, w2, y);
    }
}

// round 12
// speedup vs baseline: 1.6040x; 1.0380x over previous
#include <cuda_runtime.h>
#include <cuda_fp16.h>
#include <cstdint>

// ---------------- problem constants ----------------
#define B_SZ   8
#define T_LEN  4096
#define D_INP  256
#define D_OUTP 256
#define N_ST   512
#define M_TOT  (B_SZ * T_LEN)      // 32768
#define NBU    (2 * N_ST)          // 1024
#define KCAT   (NBU + D_INP)       // 1280
#define CHUNK  128
#define NCHUNK (T_LEN / CHUNK)     // 32

// ---------------- device scratch ----------------
// A2 layout: cols [0,1024) = X interleaved (2n = xr_n, 2n+1 = xi_n), cols [1024,1280) = u
__device__ __half g_A2[(size_t)M_TOT * KCAT];
__device__ __half g_B1[NBU * D_INP];             // gamma-scaled B, interleaved rows
__device__ __half g_W2[D_OUTP * KCAT];           // K-interleaved [2Cr/-2Ci | D]
__device__ float2 g_lam [N_ST];
__device__ float2 g_lamL[N_ST];
__device__ float2 g_F    [B_SZ * NCHUNK * N_ST];
__device__ float2 g_carry[B_SZ * NCHUNK * N_ST];

// ---------------- helpers ----------------
__device__ __forceinline__ uint32_t smem_u32(const void* p) {
    uint32_t a;
    asm("{ .reg .u64 t; cvta.to.shared.u64 t, %1; cvt.u32.u64 %0, t; }" : "=r"(a) : "l"(p));
    return a;
}

#define CP_ASYNC16(dst, src) \
    asm volatile("cp.async.cg.shared.global [%0], [%1], 16;" :: "r"(dst), "l"(src))
#define CP_COMMIT() asm volatile("cp.async.commit_group;")
#define CP_WAIT2()  asm volatile("cp.async.wait_group 2;")
#define CP_WAIT0()  asm volatile("cp.async.wait_group 0;")

#define LDSM4(r0, r1, r2, r3, addr) \
    asm volatile("ldmatrix.sync.aligned.m8n8.x4.shared.b16 {%0,%1,%2,%3}, [%4];" \
        : "=r"(r0), "=r"(r1), "=r"(r2), "=r"(r3) : "r"(addr))

#define MMA16816(d, a, b0, b1) \
    asm volatile("mma.sync.aligned.m16n8k16.row.col.f32.f16.f16.f32 " \
        "{%0,%1,%2,%3}, {%4,%5,%6,%7}, {%8,%9}, {%0,%1,%2,%3};" \
        : "+f"(d[0]), "+f"(d[1]), "+f"(d[2]), "+f"(d[3]) \
        : "r"(a[0]), "r"(a[1]), "r"(a[2]), "r"(a[3]), "r"(b0), "r"(b1))

// ---------------- setup kernels ----------------
__global__ void k_setup(const float* __restrict__ nu_log,
                        const float* __restrict__ theta_log) {
    int n = blockIdx.x * blockDim.x + threadIdx.x;
    if (n >= N_ST) return;
    float lm = expf(-expf(nu_log[n]));
    float th = expf(theta_log[n]);
    float2 lam = make_float2(lm * cosf(th), lm * sinf(th));
    g_lam[n] = lam;
    float2 p = lam;
#pragma unroll
    for (int i = 0; i < 7; i++) {
        float2 q;
        q.x = p.x * p.x - p.y * p.y;
        q.y = 2.0f * p.x * p.y;
        p = q;
    }
    g_lamL[n] = p;
}

// merged weight prep
#define B1_ELEMS (NBU * D_INP)
#define W2_ELEMS (D_OUTP * KCAT)
__global__ void k_prepW(const float* __restrict__ gamma_log,
                        const float* __restrict__ Br,
                        const float* __restrict__ Bi,
                        const float* __restrict__ Cr,
                        const float* __restrict__ Ci,
                        const float* __restrict__ Dm) {
    int idx = blockIdx.x * blockDim.x + threadIdx.x;
    if (idx < B1_ELEMS) {
        int nn = idx / D_INP, i = idx % D_INP;
        int n = nn >> 1;
        float g = expf(gamma_log[n]);
        float v = g * (((nn & 1) == 0) ? Br[n * D_INP + i] : Bi[n * D_INP + i]);
        g_B1[idx] = __float2half_rn(v);
    } else if (idx < B1_ELEMS + W2_ELEMS) {
        int j = idx - B1_ELEMS;
        int o = j / KCAT, k = j % KCAT;
        float v;
        if (k < NBU) {
            int n = k >> 1;
            v = ((k & 1) == 0) ? 2.0f * Cr[o * N_ST + n] : -2.0f * Ci[o * N_ST + n];
        } else {
            v = Dm[o * D_INP + (k - NBU)];
        }
        g_W2[j] = __float2half_rn(v);
    }
}

__global__ void k_cvtU(const float* __restrict__ u) {
    int idx = blockIdx.x * blockDim.x + threadIdx.x;
    if (idx >= M_TOT * D_INP / 4) return;
    int m = idx / (D_INP / 4), i = (idx % (D_INP / 4)) * 4;
    float4 v = *(const float4*)(u + (size_t)m * D_INP + i);
    __half2 h0 = __floats2half2_rn(v.x, v.y);
    __half2 h1 = __floats2half2_rn(v.z, v.w);
    __half2* dst = (__half2*)(g_A2 + (size_t)m * KCAT + NBU + i);
    dst[0] = h0;
    dst[1] = h1;
}

// ---------------- GEMM mainloop: CTA 128(M) x 128(N), BK=32, 256 threads ----------------
// 8 warps as 2(m) x 4(n); warp tile 64x32; mma.m16n8k16; acc[4][4][4] (64 regs).
// __launch_bounds__(256, 2): regs capped at 128 -> 2 CTAs/SM (smem 80KB each).
#define NTHREADS 256
#define BK       32
#define PADK     40                       // padded k-stride (elems)
#define TILE_T_B (128 * PADK * 2)         // 10240 B per tile (A or B)
#define STAGE_B  (2 * TILE_T_B)           // 20480 B
#define STAGES   4
#define SMEM_GEMM (STAGES * STAGE_B)      // 81920 B

__device__ __forceinline__ void gemm_mainloop(
    uint32_t sb, const __half* A0, const __half* B0,
    int K, int lda, int ldb, float acc[4][4][4],
    int tid, int wm, int wn, int lid) {

    const int NC = K / BK;

    auto issue_load = [&](int c) {
        const int s = c % STAGES;
        const uint32_t stb = sb + s * STAGE_B;
        const int k0 = c * BK;
#pragma unroll
        for (int r = 0; r < 2; r++) {                // A: 512 chunks
            int idx = tid + r * NTHREADS;
            int row = idx >> 2, ch = idx & 3;
            uint32_t soff = (uint32_t)(row * (PADK * 2) + ch * 16);
            CP_ASYNC16(stb + soff, A0 + (size_t)row * lda + k0 + ch * 8);
        }
#pragma unroll
        for (int r = 0; r < 2; r++) {                // B: 512 chunks
            int idx = tid + r * NTHREADS;
            int row = idx >> 2, ch = idx & 3;
            uint32_t soff = (uint32_t)(row * (PADK * 2) + ch * 16);
            CP_ASYNC16(stb + TILE_T_B + soff, B0 + (size_t)row * ldb + k0 + ch * 8);
        }
        CP_COMMIT();
    };

    const int aRow = lid & 15;
    const int aCol = (lid >> 4) << 3;
    const int bRow = (lid & 7) + ((lid >> 4) << 3);
    const int bCol = ((lid >> 3) & 1) << 3;

    issue_load(0);
    issue_load(1);
    issue_load(2);

    for (int c = 0; c < NC; c++) {
        CP_WAIT2();
        __syncthreads();
        if (c + 3 < NC) issue_load(c + 3);
        else            CP_COMMIT();

        const uint32_t stb = sb + (c % STAGES) * STAGE_B;
        const uint32_t sA = stb;
        const uint32_t sB = stb + TILE_T_B;

#pragma unroll
        for (int kk = 0; kk < BK; kk += 16) {
            uint32_t a[4][4], b[2][4];
#pragma unroll
            for (int mf = 0; mf < 4; mf++) {
                uint32_t ad = sA + (uint32_t)((wm * 64 + mf * 16 + aRow) * (PADK * 2) + (kk + aCol) * 2);
                LDSM4(a[mf][0], a[mf][1], a[mf][2], a[mf][3], ad);
            }
#pragma unroll
            for (int p = 0; p < 2; p++) {
                uint32_t bd = sB + (uint32_t)((wn * 32 + p * 16 + bRow) * (PADK * 2) + (kk + bCol) * 2);
                LDSM4(b[p][0], b[p][1], b[p][2], b[p][3], bd);
            }
#pragma unroll
            for (int mf = 0; mf < 4; mf++)
#pragma unroll
                for (int nf = 0; nf < 4; nf++)
                    MMA16816(acc[mf][nf], a[mf], b[nf >> 1][(nf & 1) * 2], b[nf >> 1][(nf & 1) * 2 + 1]);
        }
        __syncthreads();
    }
    CP_WAIT0();
}

// ---------------- GEMM1 + fused chunk-local scan (64 states per tile) ----------------
#define SCAN_STRIDE 136
#define SMEM_SCAN   (128 * SCAN_STRIDE * 4)   // 69632 B <= SMEM_GEMM

__global__ __launch_bounds__(NTHREADS, 2)
void gemm1_scan(const __half* __restrict__ A,
                const __half* __restrict__ B) {
    extern __shared__ char smem[];
    const uint32_t sb = smem_u32(smem);
    const int tid = threadIdx.x;
    const int wid = tid >> 5, lid = tid & 31;
    const int m0 = blockIdx.y * 128;
    const int n0 = blockIdx.x * 128;
    const int wm = wid >> 2, wn = wid & 3;

    float acc[4][4][4];
#pragma unroll
    for (int i = 0; i < 4; i++)
#pragma unroll
        for (int j = 0; j < 4; j++)
#pragma unroll
            for (int q = 0; q < 4; q++) acc[i][j][q] = 0.0f;

    gemm_mainloop(sb, A + (size_t)m0 * KCAT, B + (size_t)n0 * D_INP,
                  D_INP, KCAT, D_INP, acc, tid, wm, wn, lid);

    __syncthreads();            // pipeline smem dead, reuse for scan buffer

    float* sc = (float*)smem;   // [128][SCAN_STRIDE]
    const int gid = lid >> 2, tig = lid & 3;
#pragma unroll
    for (int mf = 0; mf < 4; mf++) {
        const int row = wm * 64 + mf * 16 + gid;
#pragma unroll
        for (int nf = 0; nf < 4; nf++) {
            const int col = wn * 32 + nf * 8 + tig * 2;
            *(float2*)(sc + row * SCAN_STRIDE + col) =
                make_float2(acc[mf][nf][0], acc[mf][nf][1]);
            *(float2*)(sc + (row + 8) * SCAN_STRIDE + col) =
                make_float2(acc[mf][nf][2], acc[mf][nf][3]);
        }
    }
    __syncthreads();

    // chunk-local complex scan: 64 complex pairs in this tile
    if (tid < 64) {
        const int np = (n0 >> 1) + tid;         // global state index
        const float2 lam = g_lam[np];
        const int b = m0 >> 12;                 // / T_LEN
        const int c = (m0 & (T_LEN - 1)) >> 7;  // / CHUNK
        float xr = 0.0f, xi = 0.0f;
        __half* out = g_A2 + (size_t)m0 * KCAT + 2 * np;
#pragma unroll 4
        for (int t = 0; t < CHUNK; t++) {
            float2 bu = *(const float2*)(sc + t * SCAN_STRIDE + 2 * tid);
            float nxr = fmaf(lam.x, xr, fmaf(-lam.y, xi, bu.x));
            float nxi = fmaf(lam.x, xi, fmaf(lam.y, xr, bu.y));
            xr = nxr; xi = nxi;
            *(__half2*)(out + (size_t)t * KCAT) = __floats2half2_rn(xr, xi);
        }
        g_F[(b * NCHUNK + c) * N_ST + np] = make_float2(xr, xi);
    }
}

// ---------------- GEMM2: y[M,256] = A2 @ W2^T ----------------
__global__ __launch_bounds__(NTHREADS, 2)
void gemm2_out(const __half* __restrict__ A,
               const __half* __restrict__ B,
               float* __restrict__ C) {
    extern __shared__ char smem[];
    const uint32_t sb = smem_u32(smem);
    const int tid = threadIdx.x;
    const int wid = tid >> 5, lid = tid & 31;
    const int m0 = blockIdx.y * 128;
    const int n0 = blockIdx.x * 128;
    const int wm = wid >> 2, wn = wid & 3;

    float acc[4][4][4];
#pragma unroll
    for (int i = 0; i < 4; i++)
#pragma unroll
        for (int j = 0; j < 4; j++)
#pragma unroll
            for (int q = 0; q < 4; q++) acc[i][j][q] = 0.0f;

    gemm_mainloop(sb, A + (size_t)m0 * KCAT, B + (size_t)n0 * KCAT,
                  KCAT, KCAT, KCAT, acc, tid, wm, wn, lid);

    const int gid = lid >> 2, tig = lid & 3;
#pragma unroll
    for (int mf = 0; mf < 4; mf++) {
        const int row = m0 + wm * 64 + mf * 16 + gid;
#pragma unroll
        for (int nf = 0; nf < 4; nf++) {
            const int col = n0 + wn * 32 + nf * 8 + tig * 2;
            *(float2*)(C + (size_t)row * D_OUTP + col) =
                make_float2(acc[mf][nf][0], acc[mf][nf][1]);
            *(float2*)(C + (size_t)(row + 8) * D_OUTP + col) =
                make_float2(acc[mf][nf][2], acc[mf][nf][3]);
        }
    }
}

// ---------------- chunk-level prefix over finals ----------------
__global__ void k_chunk_prefix() {
    int id = blockIdx.x * blockDim.x + threadIdx.x;
    if (id >= B_SZ * N_ST) return;
    int n = id & (N_ST - 1);
    int b = id >> 9;
    float2 lamL = g_lamL[n];
    float sr = 0.0f, si = 0.0f;
#pragma unroll
    for (int c = 0; c < NCHUNK; c++) {
        int idx = (b * NCHUNK + c) * N_ST + n;
        g_carry[idx] = make_float2(sr, si);
        float2 f = g_F[idx];
        float nsr = fmaf(lamL.x, sr, fmaf(-lamL.y, si, f.x));
        float nsi = fmaf(lamL.x, si, fmaf(lamL.y, sr, f.y));
        sr = nsr; si = nsi;
    }
}

// ---------------- carry correction: x_t += lam^{t+1} * carry ----------------
__global__ void k_correct() {
    int id = blockIdx.x * blockDim.x + threadIdx.x;
    if (id >= B_SZ * NCHUNK * (N_ST / 2)) return;
    int sp = id & (N_ST / 2 - 1);             // state pair 0..255
    int c = (id >> 8) & (NCHUNK - 1);
    int b = id >> 13;
    if (c == 0) return;                       // carry is zero for chunk 0
    const int np0 = 2 * sp, np1 = 2 * sp + 1;
    const int cbase = (b * NCHUNK + c) * N_ST;
    float2 ca = g_carry[cbase + np0];
    float2 cb = g_carry[cbase + np1];
    float2 la = g_lam[np0];
    float2 lb = g_lam[np1];
    float ar = ca.x, ai = ca.y;
    float br = cb.x, bi = cb.y;
    __half2* xp = (__half2*)(g_A2 + ((size_t)(b * T_LEN + c * CHUNK)) * KCAT + 4 * sp);
    const int stride2 = KCAT / 2;             // __half2 stride per t
#pragma unroll 4
    for (int t = 0; t < CHUNK; t++) {
        float nar = ar * la.x - ai * la.y;
        float nai = ar * la.y + ai * la.x;
        ar = nar; ai = nai;
        float nbr = br * lb.x - bi * lb.y;
        float nbi = br * lb.y + bi * lb.x;
        br = nbr; bi = nbi;
        uint2* up = (uint2*)(xp + (size_t)t * stride2);
        uint2 raw = *up;
        __half2 v0 = *(__half2*)&raw.x;
        __half2 v1 = *(__half2*)&raw.y;
        float2 x0 = __half22float2(v0);
        float2 x1 = __half22float2(v1);
        __half2 o0 = __floats2half2_rn(x0.x + ar, x0.y + ai);
        __half2 o1 = __floats2half2_rn(x1.x + br, x1.y + bi);
        uint2 out;
        out.x = *(uint32_t*)&o0;
        out.y = *(uint32_t*)&o1;
        *up = out;
    }
}

// ---------------- launch ----------------
extern "C" void kernel_launch(void* const* d_in, const int* in_sizes, int n_in,
                              void* d_out, int out_size) {
    const float* u_in      = (const float*)d_in[0];
    const float* nu_log    = (const float*)d_in[1];
    const float* theta_log = (const float*)d_in[2];
    const float* gamma_log = (const float*)d_in[3];
    const float* B_real    = (const float*)d_in[4];
    const float* B_imag    = (const float*)d_in[5];
    const float* C_real    = (const float*)d_in[6];
    const float* C_imag    = (const float*)d_in[7];
    const float* Dm        = (const float*)d_in[8];
    float* y = (float*)d_out;

    __half *a2, *b1, *w2;
    cudaGetSymbolAddress((void**)&a2, g_A2);
    cudaGetSymbolAddress((void**)&b1, g_B1);
    cudaGetSymbolAddress((void**)&w2, g_W2);

    cudaFuncSetAttribute(gemm1_scan,
                         cudaFuncAttributeMaxDynamicSharedMemorySize, SMEM_GEMM);
    cudaFuncSetAttribute(gemm2_out,
                         cudaFuncAttributeMaxDynamicSharedMemorySize, SMEM_GEMM);

    // setup / conversions
    k_setup<<<2, 256>>>(nu_log, theta_log);
    k_prepW<<<(B1_ELEMS + W2_ELEMS + 255) / 256, 256>>>(gamma_log, B_real, B_imag,
                                                        C_real, C_imag, Dm);
    k_cvtU<<<(M_TOT * D_INP / 4 + 255) / 256, 256>>>(u_in);

    // GEMM1 + chunk-local scan: writes X_local (fp16) into A2 and chunk finals
    {
        dim3 grid(NBU / 128, M_TOT / 128);
        gemm1_scan<<<grid, NTHREADS, SMEM_GEMM>>>(a2 + NBU, b1);
    }

    // chunk prefix + carry correction
    k_chunk_prefix<<<(B_SZ * N_ST + 255) / 256, 256>>>();
    k_correct<<<(B_SZ * NCHUNK * (N_ST / 2) + 255) / 256, 256>>>();

    // GEMM 2: y[M, 256] = [X | u] @ W2^T, K=1280
    {
        dim3 grid(D_OUTP / 128, M_TOT / 128);
        gemm2_out<<<grid, NTHREADS, SMEM_GEMM>>>(a2, w2, y);
    }
}

// round 13
// speedup vs baseline: 1.6756x; 1.0447x over previous
#include <cuda_runtime.h>
#include <cuda_fp16.h>
#include <cstdint>

// ---------------- problem constants ----------------
#define B_SZ   8
#define T_LEN  4096
#define D_INP  256
#define D_OUTP 256
#define N_ST   512
#define M_TOT  (B_SZ * T_LEN)      // 32768
#define NBU    (2 * N_ST)          // 1024
#define KCAT   (NBU + D_INP)       // 1280
#define CHUNK  128
#define NCHUNK (T_LEN / CHUNK)     // 32

// ---------------- device scratch ----------------
// A2 layout: cols [0,1024) = X interleaved (2n = xr_n, 2n+1 = xi_n), cols [1024,1280) = u
__device__ __half g_A2[(size_t)M_TOT * KCAT];
__device__ __half g_B1[NBU * D_INP];             // gamma-scaled B, interleaved rows
__device__ __half g_W2[D_OUTP * KCAT];           // K-interleaved [2Cr/-2Ci | D]
__device__ float2 g_lam  [N_ST];
__device__ float2 g_lam64[N_ST];                 // lam^64
__device__ float2 g_lamL [N_ST];                 // lam^128
__device__ float2 g_F    [B_SZ * NCHUNK * N_ST];
__device__ float2 g_carry[B_SZ * NCHUNK * N_ST];

// ---------------- helpers ----------------
__device__ __forceinline__ uint32_t smem_u32(const void* p) {
    uint32_t a;
    asm("{ .reg .u64 t; cvta.to.shared.u64 t, %1; cvt.u32.u64 %0, t; }" : "=r"(a) : "l"(p));
    return a;
}

#define CP_ASYNC16(dst, src) \
    asm volatile("cp.async.cg.shared.global [%0], [%1], 16;" :: "r"(dst), "l"(src))
#define CP_COMMIT() asm volatile("cp.async.commit_group;")
#define CP_WAIT3()  asm volatile("cp.async.wait_group 3;")
#define CP_WAIT0()  asm volatile("cp.async.wait_group 0;")

#define LDSM4(r0, r1, r2, r3, addr) \
    asm volatile("ldmatrix.sync.aligned.m8n8.x4.shared.b16 {%0,%1,%2,%3}, [%4];" \
        : "=r"(r0), "=r"(r1), "=r"(r2), "=r"(r3) : "r"(addr))

#define MMA16816(d, a, b0, b1) \
    asm volatile("mma.sync.aligned.m16n8k16.row.col.f32.f16.f16.f32 " \
        "{%0,%1,%2,%3}, {%4,%5,%6,%7}, {%8,%9}, {%0,%1,%2,%3};" \
        : "+f"(d[0]), "+f"(d[1]), "+f"(d[2]), "+f"(d[3]) \
        : "r"(a[0]), "r"(a[1]), "r"(a[2]), "r"(a[3]), "r"(b0), "r"(b1))

// ---------------- merged setup + weight prep ----------------
#define B1_ELEMS (NBU * D_INP)
#define W2_ELEMS (D_OUTP * KCAT)
__global__ void k_prep(const float* __restrict__ nu_log,
                       const float* __restrict__ theta_log,
                       const float* __restrict__ gamma_log,
                       const float* __restrict__ Br,
                       const float* __restrict__ Bi,
                       const float* __restrict__ Cr,
                       const float* __restrict__ Ci,
                       const float* __restrict__ Dm) {
    int idx = blockIdx.x * blockDim.x + threadIdx.x;
    if (idx < N_ST) {
        int n = idx;
        float lm = expf(-expf(nu_log[n]));
        float th = expf(theta_log[n]);
        float2 lam = make_float2(lm * cosf(th), lm * sinf(th));
        g_lam[n] = lam;
        float2 p = lam;
#pragma unroll
        for (int i = 0; i < 6; i++) {
            float2 q;
            q.x = p.x * p.x - p.y * p.y;
            q.y = 2.0f * p.x * p.y;
            p = q;
        }
        g_lam64[n] = p;                      // lam^64
        float2 q;
        q.x = p.x * p.x - p.y * p.y;
        q.y = 2.0f * p.x * p.y;
        g_lamL[n] = q;                       // lam^128
    } else if (idx < N_ST + B1_ELEMS) {
        int j = idx - N_ST;
        int nn = j / D_INP, i = j % D_INP;
        int n = nn >> 1;
        float g = expf(gamma_log[n]);
        float v = g * (((nn & 1) == 0) ? Br[n * D_INP + i] : Bi[n * D_INP + i]);
        g_B1[j] = __float2half_rn(v);
    } else if (idx < N_ST + B1_ELEMS + W2_ELEMS) {
        int j = idx - N_ST - B1_ELEMS;
        int o = j / KCAT, k = j % KCAT;
        float v;
        if (k < NBU) {
            int n = k >> 1;
            v = ((k & 1) == 0) ? 2.0f * Cr[o * N_ST + n] : -2.0f * Ci[o * N_ST + n];
        } else {
            v = Dm[o * D_INP + (k - NBU)];
        }
        g_W2[j] = __float2half_rn(v);
    }
}

__global__ void k_cvtU(const float* __restrict__ u) {
    int idx = blockIdx.x * blockDim.x + threadIdx.x;
    if (idx >= M_TOT * D_INP / 4) return;
    int m = idx / (D_INP / 4), i = (idx % (D_INP / 4)) * 4;
    float4 v = *(const float4*)(u + (size_t)m * D_INP + i);
    __half2 h0 = __floats2half2_rn(v.x, v.y);
    __half2 h1 = __floats2half2_rn(v.z, v.w);
    __half2* dst = (__half2*)(g_A2 + (size_t)m * KCAT + NBU + i);
    dst[0] = h0;
    dst[1] = h1;
}

// ---------------- GEMM mainloop: CTA 128(M) x 128(N), BK=32, 256 threads ----------------
// 8 warps as 2(m) x 4(n); warp tile 64x32; mma.m16n8k16; acc[4][4][4].
// 5-stage cp.async pipeline (4 in flight), ONE __syncthreads per k-chunk.
#define NTHREADS 256
#define BK       32
#define PADK     40                       // padded k-stride (elems)
#define TILE_T_B (128 * PADK * 2)         // 10240 B per tile (A or B)
#define STAGE_B  (2 * TILE_T_B)           // 20480 B
#define STAGES   5
#define SMEM_GEMM (STAGES * STAGE_B)      // 102400 B

__device__ __forceinline__ void gemm_mainloop(
    uint32_t sb, const __half* A0, const __half* B0,
    int K, int lda, int ldb, float acc[4][4][4],
    int tid, int wm, int wn, int lid) {

    const int NC = K / BK;

    auto issue_load = [&](int c) {
        const int s = c % STAGES;
        const uint32_t stb = sb + s * STAGE_B;
        const int k0 = c * BK;
#pragma unroll
        for (int r = 0; r < 2; r++) {                // A: 512 chunks
            int idx = tid + r * NTHREADS;
            int row = idx >> 2, ch = idx & 3;
            uint32_t soff = (uint32_t)(row * (PADK * 2) + ch * 16);
            CP_ASYNC16(stb + soff, A0 + (size_t)row * lda + k0 + ch * 8);
        }
#pragma unroll
        for (int r = 0; r < 2; r++) {                // B: 512 chunks
            int idx = tid + r * NTHREADS;
            int row = idx >> 2, ch = idx & 3;
            uint32_t soff = (uint32_t)(row * (PADK * 2) + ch * 16);
            CP_ASYNC16(stb + TILE_T_B + soff, B0 + (size_t)row * ldb + k0 + ch * 8);
        }
        CP_COMMIT();
    };

    const int aRow = lid & 15;
    const int aCol = (lid >> 4) << 3;
    const int bRow = (lid & 7) + ((lid >> 4) << 3);
    const int bCol = ((lid >> 3) & 1) << 3;

    issue_load(0);
    issue_load(1);
    issue_load(2);
    issue_load(3);

    for (int c = 0; c < NC; c++) {
        CP_WAIT3();
        __syncthreads();                   // single barrier per k-chunk
        if (c + 4 < NC) issue_load(c + 4);
        else            CP_COMMIT();       // keep group-count invariant

        const uint32_t stb = sb + (c % STAGES) * STAGE_B;
        const uint32_t sA = stb;
        const uint32_t sB = stb + TILE_T_B;

#pragma unroll
        for (int kk = 0; kk < BK; kk += 16) {
            uint32_t a[4][4], b[2][4];
#pragma unroll
            for (int mf = 0; mf < 4; mf++) {
                uint32_t ad = sA + (uint32_t)((wm * 64 + mf * 16 + aRow) * (PADK * 2) + (kk + aCol) * 2);
                LDSM4(a[mf][0], a[mf][1], a[mf][2], a[mf][3], ad);
            }
#pragma unroll
            for (int p = 0; p < 2; p++) {
                uint32_t bd = sB + (uint32_t)((wn * 32 + p * 16 + bRow) * (PADK * 2) + (kk + bCol) * 2);
                LDSM4(b[p][0], b[p][1], b[p][2], b[p][3], bd);
            }
#pragma unroll
            for (int mf = 0; mf < 4; mf++)
#pragma unroll
                for (int nf = 0; nf < 4; nf++)
                    MMA16816(acc[mf][nf], a[mf], b[nf >> 1][(nf & 1) * 2], b[nf >> 1][(nf & 1) * 2 + 1]);
        }
    }
    CP_WAIT0();
}

// ---------------- GEMM1 + fused chunk-local scan (64 states per tile) ----------------
#define SCAN_STRIDE 136
#define SMEM_SCAN   (128 * SCAN_STRIDE * 4)   // 69632 B <= SMEM_GEMM

__global__ __launch_bounds__(NTHREADS, 2)
void gemm1_scan(const __half* __restrict__ A,
                const __half* __restrict__ B) {
    extern __shared__ char smem[];
    const uint32_t sb = smem_u32(smem);
    const int tid = threadIdx.x;
    const int wid = tid >> 5, lid = tid & 31;
    const int m0 = blockIdx.y * 128;
    const int n0 = blockIdx.x * 128;
    const int wm = wid >> 2, wn = wid & 3;

    float acc[4][4][4];
#pragma unroll
    for (int i = 0; i < 4; i++)
#pragma unroll
        for (int j = 0; j < 4; j++)
#pragma unroll
            for (int q = 0; q < 4; q++) acc[i][j][q] = 0.0f;

    gemm_mainloop(sb, A + (size_t)m0 * KCAT, B + (size_t)n0 * D_INP,
                  D_INP, KCAT, D_INP, acc, tid, wm, wn, lid);

    __syncthreads();            // drain: pipeline smem dead, reuse for scan buffer

    float* sc = (float*)smem;   // [128][SCAN_STRIDE]
    const int gid = lid >> 2, tig = lid & 3;
#pragma unroll
    for (int mf = 0; mf < 4; mf++) {
        const int row = wm * 64 + mf * 16 + gid;
#pragma unroll
        for (int nf = 0; nf < 4; nf++) {
            const int col = wn * 32 + nf * 8 + tig * 2;
            *(float2*)(sc + row * SCAN_STRIDE + col) =
                make_float2(acc[mf][nf][0], acc[mf][nf][1]);
            *(float2*)(sc + (row + 8) * SCAN_STRIDE + col) =
                make_float2(acc[mf][nf][2], acc[mf][nf][3]);
        }
    }
    __syncthreads();

    // chunk-local complex scan: 64 complex pairs in this tile
    if (tid < 64) {
        const int np = (n0 >> 1) + tid;         // global state index
        const float2 lam = g_lam[np];
        const int b = m0 >> 12;                 // / T_LEN
        const int c = (m0 & (T_LEN - 1)) >> 7;  // / CHUNK
        float xr = 0.0f, xi = 0.0f;
        __half* out = g_A2 + (size_t)m0 * KCAT + 2 * np;
#pragma unroll 4
        for (int t = 0; t < CHUNK; t++) {
            float2 bu = *(const float2*)(sc + t * SCAN_STRIDE + 2 * tid);
            float nxr = fmaf(lam.x, xr, fmaf(-lam.y, xi, bu.x));
            float nxi = fmaf(lam.x, xi, fmaf(lam.y, xr, bu.y));
            xr = nxr; xi = nxi;
            *(__half2*)(out + (size_t)t * KCAT) = __floats2half2_rn(xr, xi);
        }
        g_F[(b * NCHUNK + c) * N_ST + np] = make_float2(xr, xi);
    }
}

// ---------------- GEMM2: y[M,256] = A2 @ W2^T ----------------
__global__ __launch_bounds__(NTHREADS, 2)
void gemm2_out(const __half* __restrict__ A,
               const __half* __restrict__ B,
               float* __restrict__ C) {
    extern __shared__ char smem[];
    const uint32_t sb = smem_u32(smem);
    const int tid = threadIdx.x;
    const int wid = tid >> 5, lid = tid & 31;
    const int m0 = blockIdx.y * 128;
    const int n0 = blockIdx.x * 128;
    const int wm = wid >> 2, wn = wid & 3;

    float acc[4][4][4];
#pragma unroll
    for (int i = 0; i < 4; i++)
#pragma unroll
        for (int j = 0; j < 4; j++)
#pragma unroll
            for (int q = 0; q < 4; q++) acc[i][j][q] = 0.0f;

    gemm_mainloop(sb, A + (size_t)m0 * KCAT, B + (size_t)n0 * KCAT,
                  KCAT, KCAT, KCAT, acc, tid, wm, wn, lid);

    const int gid = lid >> 2, tig = lid & 3;
#pragma unroll
    for (int mf = 0; mf < 4; mf++) {
        const int row = m0 + wm * 64 + mf * 16 + gid;
#pragma unroll
        for (int nf = 0; nf < 4; nf++) {
            const int col = n0 + wn * 32 + nf * 8 + tig * 2;
            *(float2*)(C + (size_t)row * D_OUTP + col) =
                make_float2(acc[mf][nf][0], acc[mf][nf][1]);
            *(float2*)(C + (size_t)(row + 8) * D_OUTP + col) =
                make_float2(acc[mf][nf][2], acc[mf][nf][3]);
        }
    }
}

// ---------------- chunk-level prefix over finals ----------------
__global__ void k_chunk_prefix() {
    int id = blockIdx.x * blockDim.x + threadIdx.x;
    if (id >= B_SZ * N_ST) return;
    int n = id & (N_ST - 1);
    int b = id >> 9;
    float2 lamL = g_lamL[n];
    float sr = 0.0f, si = 0.0f;
#pragma unroll
    for (int c = 0; c < NCHUNK; c++) {
        int idx = (b * NCHUNK + c) * N_ST + n;
        g_carry[idx] = make_float2(sr, si);
        float2 f = g_F[idx];
        float nsr = fmaf(lamL.x, sr, fmaf(-lamL.y, si, f.x));
        float nsi = fmaf(lamL.x, si, fmaf(lamL.y, sr, f.y));
        sr = nsr; si = nsi;
    }
}

// ---------------- carry correction: x_t += lam^{t+1} * carry ----------------
// 2 states per thread, t-range split in half (upper half seeds carry*lam^64).
__global__ void k_correct() {
    int id = blockIdx.x * blockDim.x + threadIdx.x;
    if (id >= B_SZ * NCHUNK * (N_ST / 2) * 2) return;
    int sp = id & (N_ST / 2 - 1);             // state pair 0..255
    int h  = (id >> 8) & 1;                   // t-half
    int c  = (id >> 9) & (NCHUNK - 1);
    int b  = id >> 14;
    if (c == 0) return;                       // carry is zero for chunk 0
    const int np0 = 2 * sp, np1 = 2 * sp + 1;
    const int cbase = (b * NCHUNK + c) * N_ST;
    float2 ca = g_carry[cbase + np0];
    float2 cb = g_carry[cbase + np1];
    float2 la = g_lam[np0];
    float2 lb = g_lam[np1];
    float ar = ca.x, ai = ca.y;
    float br = cb.x, bi = cb.y;
    if (h) {                                   // seed with lam^64
        float2 pa = g_lam64[np0], pb = g_lam64[np1];
        float t0 = ar * pa.x - ai * pa.y;
        ai = ar * pa.y + ai * pa.x; ar = t0;
        float t1 = br * pb.x - bi * pb.y;
        bi = br * pb.y + bi * pb.x; br = t1;
    }
    __half2* xp = (__half2*)(g_A2 + ((size_t)(b * T_LEN + c * CHUNK + h * 64)) * KCAT + 4 * sp);
    const int stride2 = KCAT / 2;             // __half2 stride per t
#pragma unroll 4
    for (int t = 0; t < 64; t++) {
        float nar = ar * la.x - ai * la.y;
        float nai = ar * la.y + ai * la.x;
        ar = nar; ai = nai;
        float nbr = br * lb.x - bi * lb.y;
        float nbi = br * lb.y + bi * lb.x;
        br = nbr; bi = nbi;
        uint2* up = (uint2*)(xp + (size_t)t * stride2);
        uint2 raw = *up;
        __half2 v0 = *(__half2*)&raw.x;
        __half2 v1 = *(__half2*)&raw.y;
        float2 x0 = __half22float2(v0);
        float2 x1 = __half22float2(v1);
        __half2 o0 = __floats2half2_rn(x0.x + ar, x0.y + ai);
        __half2 o1 = __floats2half2_rn(x1.x + br, x1.y + bi);
        uint2 out;
        out.x = *(uint32_t*)&o0;
        out.y = *(uint32_t*)&o1;
        *up = out;
    }
}

// ---------------- launch ----------------
extern "C" void kernel_launch(void* const* d_in, const int* in_sizes, int n_in,
                              void* d_out, int out_size) {
    const float* u_in      = (const float*)d_in[0];
    const float* nu_log    = (const float*)d_in[1];
    const float* theta_log = (const float*)d_in[2];
    const float* gamma_log = (const float*)d_in[3];
    const float* B_real    = (const float*)d_in[4];
    const float* B_imag    = (const float*)d_in[5];
    const float* C_real    = (const float*)d_in[6];
    const float* C_imag    = (const float*)d_in[7];
    const float* Dm        = (const float*)d_in[8];
    float* y = (float*)d_out;

    __half *a2, *b1, *w2;
    cudaGetSymbolAddress((void**)&a2, g_A2);
    cudaGetSymbolAddress((void**)&b1, g_B1);
    cudaGetSymbolAddress((void**)&w2, g_W2);

    cudaFuncSetAttribute(gemm1_scan,
                         cudaFuncAttributeMaxDynamicSharedMemorySize, SMEM_GEMM);
    cudaFuncSetAttribute(gemm2_out,
                         cudaFuncAttributeMaxDynamicSharedMemorySize, SMEM_GEMM);

    // merged setup + weight prep, then u conversion
    k_prep<<<(N_ST + B1_ELEMS + W2_ELEMS + 255) / 256, 256>>>(
        nu_log, theta_log, gamma_log, B_real, B_imag, C_real, C_imag, Dm);
    k_cvtU<<<(M_TOT * D_INP / 4 + 255) / 256, 256>>>(u_in);

    // GEMM1 + chunk-local scan: writes X_local (fp16) into A2 and chunk finals
    {
        dim3 grid(NBU / 128, M_TOT / 128);
        gemm1_scan<<<grid, NTHREADS, SMEM_GEMM>>>(a2 + NBU, b1);
    }

    // chunk prefix + carry correction
    k_chunk_prefix<<<(B_SZ * N_ST + 255) / 256, 256>>>();
    k_correct<<<(B_SZ * NCHUNK * N_ST + 255) / 256, 256>>>();

    // GEMM 2: y[M, 256] = [X | u] @ W2^T, K=1280
    {
        dim3 grid(D_OUTP / 128, M_TOT / 128);
        gemm2_out<<<grid, NTHREADS, SMEM_GEMM>>>(a2, w2, y);
    }
}

// round 14
// speedup vs baseline: 1.7223x; 1.0279x over previous
#include <cuda_runtime.h>
#include <cuda_fp16.h>
#include <cstdint>

// ---------------- problem constants ----------------
#define B_SZ   8
#define T_LEN  4096
#define D_INP  256
#define D_OUTP 256
#define N_ST   512
#define M_TOT  (B_SZ * T_LEN)      // 32768
#define NBU    (2 * N_ST)          // 1024
#define KCAT   (NBU + D_INP)       // 1280
#define CHUNK  128
#define NCHUNK (T_LEN / CHUNK)     // 32

// ---------------- device scratch ----------------
// A2 layout: cols [0,1024) = X interleaved (2n = xr_n, 2n+1 = xi_n), cols [1024,1280) = u
__device__ __half g_A2[(size_t)M_TOT * KCAT];
__device__ __half g_B1[NBU * D_INP];             // gamma-scaled B, interleaved rows
__device__ __half g_W2[D_OUTP * KCAT];           // K-interleaved [2Cr/-2Ci | D]
__device__ float2 g_lam  [N_ST];
__device__ float2 g_lam64[N_ST];                 // lam^64
__device__ float2 g_lamL [N_ST];                 // lam^128
__device__ float2 g_F    [B_SZ * NCHUNK * N_ST];
__device__ float2 g_carry[B_SZ * NCHUNK * N_ST];

// ---------------- helpers ----------------
__device__ __forceinline__ uint32_t smem_u32(const void* p) {
    uint32_t a;
    asm("{ .reg .u64 t; cvta.to.shared.u64 t, %1; cvt.u32.u64 %0, t; }" : "=r"(a) : "l"(p));
    return a;
}

#define CP_ASYNC16(dst, src) \
    asm volatile("cp.async.cg.shared.global [%0], [%1], 16;" :: "r"(dst), "l"(src))
#define CP_COMMIT() asm volatile("cp.async.commit_group;")
#define CP_WAIT3()  asm volatile("cp.async.wait_group 3;")
#define CP_WAIT0()  asm volatile("cp.async.wait_group 0;")

#define LDSM4(r0, r1, r2, r3, addr) \
    asm volatile("ldmatrix.sync.aligned.m8n8.x4.shared.b16 {%0,%1,%2,%3}, [%4];" \
        : "=r"(r0), "=r"(r1), "=r"(r2), "=r"(r3) : "r"(addr))

#define MMA16816(d, a, b0, b1) \
    asm volatile("mma.sync.aligned.m16n8k16.row.col.f32.f16.f16.f32 " \
        "{%0,%1,%2,%3}, {%4,%5,%6,%7}, {%8,%9}, {%0,%1,%2,%3};" \
        : "+f"(d[0]), "+f"(d[1]), "+f"(d[2]), "+f"(d[3]) \
        : "r"(a[0]), "r"(a[1]), "r"(a[2]), "r"(a[3]), "r"(b0), "r"(b1))

// ---------------- merged setup + weight prep ----------------
#define B1_ELEMS (NBU * D_INP)
#define W2_ELEMS (D_OUTP * KCAT)
__global__ void k_prep(const float* __restrict__ nu_log,
                       const float* __restrict__ theta_log,
                       const float* __restrict__ gamma_log,
                       const float* __restrict__ Br,
                       const float* __restrict__ Bi,
                       const float* __restrict__ Cr,
                       const float* __restrict__ Ci,
                       const float* __restrict__ Dm) {
    int idx = blockIdx.x * blockDim.x + threadIdx.x;
    if (idx < N_ST) {
        int n = idx;
        float lm = expf(-expf(nu_log[n]));
        float th = expf(theta_log[n]);
        float2 lam = make_float2(lm * cosf(th), lm * sinf(th));
        g_lam[n] = lam;
        float2 p = lam;
#pragma unroll
        for (int i = 0; i < 6; i++) {
            float2 q;
            q.x = p.x * p.x - p.y * p.y;
            q.y = 2.0f * p.x * p.y;
            p = q;
        }
        g_lam64[n] = p;                      // lam^64
        float2 q;
        q.x = p.x * p.x - p.y * p.y;
        q.y = 2.0f * p.x * p.y;
        g_lamL[n] = q;                       // lam^128
    } else if (idx < N_ST + B1_ELEMS) {
        int j = idx - N_ST;
        int nn = j / D_INP, i = j % D_INP;
        int n = nn >> 1;
        float g = expf(gamma_log[n]);
        float v = g * (((nn & 1) == 0) ? Br[n * D_INP + i] : Bi[n * D_INP + i]);
        g_B1[j] = __float2half_rn(v);
    } else if (idx < N_ST + B1_ELEMS + W2_ELEMS) {
        int j = idx - N_ST - B1_ELEMS;
        int o = j / KCAT, k = j % KCAT;
        float v;
        if (k < NBU) {
            int n = k >> 1;
            v = ((k & 1) == 0) ? 2.0f * Cr[o * N_ST + n] : -2.0f * Ci[o * N_ST + n];
        } else {
            v = Dm[o * D_INP + (k - NBU)];
        }
        g_W2[j] = __float2half_rn(v);
    }
}

__global__ void k_cvtU(const float* __restrict__ u) {
    int idx = blockIdx.x * blockDim.x + threadIdx.x;
    if (idx >= M_TOT * D_INP / 4) return;
    int m = idx / (D_INP / 4), i = (idx % (D_INP / 4)) * 4;
    float4 v = *(const float4*)(u + (size_t)m * D_INP + i);
    __half2 h0 = __floats2half2_rn(v.x, v.y);
    __half2 h1 = __floats2half2_rn(v.z, v.w);
    __half2* dst = (__half2*)(g_A2 + (size_t)m * KCAT + NBU + i);
    dst[0] = h0;
    dst[1] = h1;
}

// ---------------- GEMM mainloop: CTA 128(M) x 128(N), BK=32, 256 threads ----------------
// 8 warps as 2(m) x 4(n); warp tile 64x32; mma.m16n8k16; acc[4][4][4].
// 5-stage cp.async pipeline (4 in flight), ONE __syncthreads per k-chunk.
#define NTHREADS 256
#define BK       32
#define PADK     40                       // padded k-stride (elems)
#define TILE_T_B (128 * PADK * 2)         // 10240 B per tile (A or B)
#define STAGE_B  (2 * TILE_T_B)           // 20480 B
#define STAGES   5
#define SMEM_GEMM (STAGES * STAGE_B)      // 102400 B

__device__ __forceinline__ void gemm_mainloop(
    uint32_t sb, const __half* A0, const __half* B0,
    int K, int lda, int ldb, float acc[4][4][4],
    int tid, int wm, int wn, int lid) {

    const int NC = K / BK;

    auto issue_load = [&](int c) {
        const int s = c % STAGES;
        const uint32_t stb = sb + s * STAGE_B;
        const int k0 = c * BK;
#pragma unroll
        for (int r = 0; r < 2; r++) {                // A: 512 chunks
            int idx = tid + r * NTHREADS;
            int row = idx >> 2, ch = idx & 3;
            uint32_t soff = (uint32_t)(row * (PADK * 2) + ch * 16);
            CP_ASYNC16(stb + soff, A0 + (size_t)row * lda + k0 + ch * 8);
        }
#pragma unroll
        for (int r = 0; r < 2; r++) {                // B: 512 chunks
            int idx = tid + r * NTHREADS;
            int row = idx >> 2, ch = idx & 3;
            uint32_t soff = (uint32_t)(row * (PADK * 2) + ch * 16);
            CP_ASYNC16(stb + TILE_T_B + soff, B0 + (size_t)row * ldb + k0 + ch * 8);
        }
        CP_COMMIT();
    };

    const int aRow = lid & 15;
    const int aCol = (lid >> 4) << 3;
    const int bRow = (lid & 7) + ((lid >> 4) << 3);
    const int bCol = ((lid >> 3) & 1) << 3;

    issue_load(0);
    issue_load(1);
    issue_load(2);
    issue_load(3);

    for (int c = 0; c < NC; c++) {
        CP_WAIT3();
        __syncthreads();                   // single barrier per k-chunk
        if (c + 4 < NC) issue_load(c + 4);
        else            CP_COMMIT();       // keep group-count invariant

        const uint32_t stb = sb + (c % STAGES) * STAGE_B;
        const uint32_t sA = stb;
        const uint32_t sB = stb + TILE_T_B;

#pragma unroll
        for (int kk = 0; kk < BK; kk += 16) {
            uint32_t a[4][4], b[2][4];
#pragma unroll
            for (int mf = 0; mf < 4; mf++) {
                uint32_t ad = sA + (uint32_t)((wm * 64 + mf * 16 + aRow) * (PADK * 2) + (kk + aCol) * 2);
                LDSM4(a[mf][0], a[mf][1], a[mf][2], a[mf][3], ad);
            }
#pragma unroll
            for (int p = 0; p < 2; p++) {
                uint32_t bd = sB + (uint32_t)((wn * 32 + p * 16 + bRow) * (PADK * 2) + (kk + bCol) * 2);
                LDSM4(b[p][0], b[p][1], b[p][2], b[p][3], bd);
            }
#pragma unroll
            for (int mf = 0; mf < 4; mf++)
#pragma unroll
                for (int nf = 0; nf < 4; nf++)
                    MMA16816(acc[mf][nf], a[mf], b[nf >> 1][(nf & 1) * 2], b[nf >> 1][(nf & 1) * 2 + 1]);
        }
    }
    CP_WAIT0();
}

// ---------------- GEMM1 + fused chunk-local scan (64 states per tile) ----------------
#define SCAN_STRIDE 136

__global__ __launch_bounds__(NTHREADS, 2)
void gemm1_scan(const __half* __restrict__ A,
                const __half* __restrict__ B) {
    extern __shared__ char smem[];
    const uint32_t sb = smem_u32(smem);
    const int tid = threadIdx.x;
    const int wid = tid >> 5, lid = tid & 31;
    const int m0 = blockIdx.y * 128;
    const int n0 = blockIdx.x * 128;
    const int wm = wid >> 2, wn = wid & 3;

    float acc[4][4][4];
#pragma unroll
    for (int i = 0; i < 4; i++)
#pragma unroll
        for (int j = 0; j < 4; j++)
#pragma unroll
            for (int q = 0; q < 4; q++) acc[i][j][q] = 0.0f;

    gemm_mainloop(sb, A + (size_t)m0 * KCAT, B + (size_t)n0 * D_INP,
                  D_INP, KCAT, D_INP, acc, tid, wm, wn, lid);

    __syncthreads();            // drain: pipeline smem dead, reuse for scan buffer

    float* sc = (float*)smem;   // [128][SCAN_STRIDE]
    const int gid = lid >> 2, tig = lid & 3;
#pragma unroll
    for (int mf = 0; mf < 4; mf++) {
        const int row = wm * 64 + mf * 16 + gid;
#pragma unroll
        for (int nf = 0; nf < 4; nf++) {
            const int col = wn * 32 + nf * 8 + tig * 2;
            *(float2*)(sc + row * SCAN_STRIDE + col) =
                make_float2(acc[mf][nf][0], acc[mf][nf][1]);
            *(float2*)(sc + (row + 8) * SCAN_STRIDE + col) =
                make_float2(acc[mf][nf][2], acc[mf][nf][3]);
        }
    }
    __syncthreads();

    // chunk-local complex scan: 64 complex pairs in this tile
    if (tid < 64) {
        const int np = (n0 >> 1) + tid;         // global state index
        const float2 lam = g_lam[np];
        const int b = m0 >> 12;                 // / T_LEN
        const int c = (m0 & (T_LEN - 1)) >> 7;  // / CHUNK
        float xr = 0.0f, xi = 0.0f;
        __half* out = g_A2 + (size_t)m0 * KCAT + 2 * np;
#pragma unroll 4
        for (int t = 0; t < CHUNK; t++) {
            float2 bu = *(const float2*)(sc + t * SCAN_STRIDE + 2 * tid);
            float nxr = fmaf(lam.x, xr, fmaf(-lam.y, xi, bu.x));
            float nxi = fmaf(lam.x, xi, fmaf(lam.y, xr, bu.y));
            xr = nxr; xi = nxi;
            *(__half2*)(out + (size_t)t * KCAT) = __floats2half2_rn(xr, xi);
        }
        g_F[(b * NCHUNK + c) * N_ST + np] = make_float2(xr, xi);
    }
}

// ---------------- GEMM2: y[M,256] = A2 @ W2^T ----------------
__global__ __launch_bounds__(NTHREADS, 2)
void gemm2_out(const __half* __restrict__ A,
               const __half* __restrict__ B,
               float* __restrict__ C) {
    extern __shared__ char smem[];
    const uint32_t sb = smem_u32(smem);
    const int tid = threadIdx.x;
    const int wid = tid >> 5, lid = tid & 31;
    const int m0 = blockIdx.y * 128;
    const int n0 = blockIdx.x * 128;
    const int wm = wid >> 2, wn = wid & 3;

    float acc[4][4][4];
#pragma unroll
    for (int i = 0; i < 4; i++)
#pragma unroll
        for (int j = 0; j < 4; j++)
#pragma unroll
            for (int q = 0; q < 4; q++) acc[i][j][q] = 0.0f;

    gemm_mainloop(sb, A + (size_t)m0 * KCAT, B + (size_t)n0 * KCAT,
                  KCAT, KCAT, KCAT, acc, tid, wm, wn, lid);

    const int gid = lid >> 2, tig = lid & 3;
#pragma unroll
    for (int mf = 0; mf < 4; mf++) {
        const int row = m0 + wm * 64 + mf * 16 + gid;
#pragma unroll
        for (int nf = 0; nf < 4; nf++) {
            const int col = n0 + wn * 32 + nf * 8 + tig * 2;
            *(float2*)(C + (size_t)row * D_OUTP + col) =
                make_float2(acc[mf][nf][0], acc[mf][nf][1]);
            *(float2*)(C + (size_t)(row + 8) * D_OUTP + col) =
                make_float2(acc[mf][nf][2], acc[mf][nf][3]);
        }
    }
}

// ---------------- chunk-level prefix: Kogge-Stone warp scan ----------------
// One warp per (b, n); lane = chunk index. Affine element (A, B): x -> A*x + B.
__global__ void k_chunk_prefix() {
    int gid = blockIdx.x * blockDim.x + threadIdx.x;
    int w = gid >> 5;                       // (b, n) index
    int lane = gid & 31;
    if (w >= B_SZ * N_ST) return;
    int n = w & (N_ST - 1);
    int b = w >> 9;

    float2 lamL = g_lamL[n];
    float2 f = g_F[(b * NCHUNK + lane) * N_ST + n];
    float ar = lamL.x, ai = lamL.y;         // A (lam^128)
    float br = f.x,    bi = f.y;            // B

#pragma unroll
    for (int d = 1; d < 32; d <<= 1) {
        float par = __shfl_up_sync(0xFFFFFFFFu, ar, d);
        float pai = __shfl_up_sync(0xFFFFFFFFu, ai, d);
        float pbr = __shfl_up_sync(0xFFFFFFFFu, br, d);
        float pbi = __shfl_up_sync(0xFFFFFFFFu, bi, d);
        if (lane >= d) {
            // cur = prev ∘ cur : A = A_cur*A_prev, B = A_cur*B_prev + B_cur
            float nbr = ar * pbr - ai * pbi + br;
            float nbi = ar * pbi + ai * pbr + bi;
            float nar = ar * par - ai * pai;
            float nai = ar * pai + ai * par;
            ar = nar; ai = nai; br = nbr; bi = nbi;
        }
    }
    // inclusive result s_lane; carry entering chunk c = s_{c-1}
    float cr = __shfl_up_sync(0xFFFFFFFFu, br, 1);
    float ci = __shfl_up_sync(0xFFFFFFFFu, bi, 1);
    if (lane == 0) { cr = 0.0f; ci = 0.0f; }
    g_carry[(b * NCHUNK + lane) * N_ST + n] = make_float2(cr, ci);
}

// ---------------- carry correction: x_t += lam^{t+1} * carry ----------------
// 2 states per thread, t-range split in half (upper half seeds carry*lam^64).
__global__ void k_correct() {
    int id = blockIdx.x * blockDim.x + threadIdx.x;
    if (id >= B_SZ * NCHUNK * (N_ST / 2) * 2) return;
    int sp = id & (N_ST / 2 - 1);             // state pair 0..255
    int h  = (id >> 8) & 1;                   // t-half
    int c  = (id >> 9) & (NCHUNK - 1);
    int b  = id >> 14;
    if (c == 0) return;                       // carry is zero for chunk 0
    const int np0 = 2 * sp, np1 = 2 * sp + 1;
    const int cbase = (b * NCHUNK + c) * N_ST;
    float2 ca = g_carry[cbase + np0];
    float2 cb = g_carry[cbase + np1];
    float2 la = g_lam[np0];
    float2 lb = g_lam[np1];
    float ar = ca.x, ai = ca.y;
    float br = cb.x, bi = cb.y;
    if (h) {                                   // seed with lam^64
        float2 pa = g_lam64[np0], pb = g_lam64[np1];
        float t0 = ar * pa.x - ai * pa.y;
        ai = ar * pa.y + ai * pa.x; ar = t0;
        float t1 = br * pb.x - bi * pb.y;
        bi = br * pb.y + bi * pb.x; br = t1;
    }
    __half2* xp = (__half2*)(g_A2 + ((size_t)(b * T_LEN + c * CHUNK + h * 64)) * KCAT + 4 * sp);
    const int stride2 = KCAT / 2;             // __half2 stride per t
#pragma unroll 4
    for (int t = 0; t < 64; t++) {
        float nar = ar * la.x - ai * la.y;
        float nai = ar * la.y + ai * la.x;
        ar = nar; ai = nai;
        float nbr = br * lb.x - bi * lb.y;
        float nbi = br * lb.y + bi * lb.x;
        br = nbr; bi = nbi;
        uint2* up = (uint2*)(xp + (size_t)t * stride2);
        uint2 raw = *up;
        __half2 v0 = *(__half2*)&raw.x;
        __half2 v1 = *(__half2*)&raw.y;
        float2 x0 = __half22float2(v0);
        float2 x1 = __half22float2(v1);
        __half2 o0 = __floats2half2_rn(x0.x + ar, x0.y + ai);
        __half2 o1 = __floats2half2_rn(x1.x + br, x1.y + bi);
        uint2 out;
        out.x = *(uint32_t*)&o0;
        out.y = *(uint32_t*)&o1;
        *up = out;
    }
}

// ---------------- launch ----------------
extern "C" void kernel_launch(void* const* d_in, const int* in_sizes, int n_in,
                              void* d_out, int out_size) {
    const float* u_in      = (const float*)d_in[0];
    const float* nu_log    = (const float*)d_in[1];
    const float* theta_log = (const float*)d_in[2];
    const float* gamma_log = (const float*)d_in[3];
    const float* B_real    = (const float*)d_in[4];
    const float* B_imag    = (const float*)d_in[5];
    const float* C_real    = (const float*)d_in[6];
    const float* C_imag    = (const float*)d_in[7];
    const float* Dm        = (const float*)d_in[8];
    float* y = (float*)d_out;

    __half *a2, *b1, *w2;
    cudaGetSymbolAddress((void**)&a2, g_A2);
    cudaGetSymbolAddress((void**)&b1, g_B1);
    cudaGetSymbolAddress((void**)&w2, g_W2);

    cudaFuncSetAttribute(gemm1_scan,
                         cudaFuncAttributeMaxDynamicSharedMemorySize, SMEM_GEMM);
    cudaFuncSetAttribute(gemm2_out,
                         cudaFuncAttributeMaxDynamicSharedMemorySize, SMEM_GEMM);

    // merged setup + weight prep, then u conversion
    k_prep<<<(N_ST + B1_ELEMS + W2_ELEMS + 255) / 256, 256>>>(
        nu_log, theta_log, gamma_log, B_real, B_imag, C_real, C_imag, Dm);
    k_cvtU<<<(M_TOT * D_INP / 4 + 255) / 256, 256>>>(u_in);

    // GEMM1 + chunk-local scan: writes X_local (fp16) into A2 and chunk finals
    {
        dim3 grid(NBU / 128, M_TOT / 128);
        gemm1_scan<<<grid, NTHREADS, SMEM_GEMM>>>(a2 + NBU, b1);
    }

    // chunk prefix (warp scan) + carry correction
    k_chunk_prefix<<<(B_SZ * N_ST * 32 + 255) / 256, 256>>>();
    k_correct<<<(B_SZ * NCHUNK * N_ST + 255) / 256, 256>>>();

    // GEMM 2: y[M, 256] = [X | u] @ W2^T, K=1280
    {
        dim3 grid(D_OUTP / 128, M_TOT / 128);
        gemm2_out<<<grid, NTHREADS, SMEM_GEMM>>>(a2, w2, y);
    }
}

// round 15
// speedup vs baseline: 1.8624x; 1.0813x over previous
#include <cuda_runtime.h>
#include <cuda_fp16.h>
#include <cstdint>

// ---------------- problem constants ----------------
#define B_SZ   8
#define T_LEN  4096
#define D_INP  256
#define D_OUTP 256
#define N_ST   512
#define M_TOT  (B_SZ * T_LEN)      // 32768
#define NBU    (2 * N_ST)          // 1024
#define KCAT   (NBU + D_INP)       // 1280
#define CHUNK  128
#define NCHUNK (T_LEN / CHUNK)     // 32

// ---------------- device scratch ----------------
// A2 layout: cols [0,1024) = X interleaved (2n = xr_n, 2n+1 = xi_n), cols [1024,1280) = u
__device__ __half g_A2[(size_t)M_TOT * KCAT];
__device__ __half g_B1[NBU * D_INP];             // gamma-scaled B, interleaved rows
__device__ __half g_W2[D_OUTP * KCAT];           // K-interleaved [2Cr/-2Ci | D]
__device__ float2 g_lam  [N_ST];
__device__ float2 g_lam64[N_ST];                 // lam^64
__device__ float2 g_lamL [N_ST];                 // lam^128
__device__ float2 g_F    [B_SZ * NCHUNK * N_ST];
__device__ float2 g_carry[B_SZ * NCHUNK * N_ST];

// ---------------- helpers ----------------
__device__ __forceinline__ uint32_t smem_u32(const void* p) {
    uint32_t a;
    asm("{ .reg .u64 t; cvta.to.shared.u64 t, %1; cvt.u32.u64 %0, t; }" : "=r"(a) : "l"(p));
    return a;
}

#define CP_ASYNC16(dst, src) \
    asm volatile("cp.async.cg.shared.global [%0], [%1], 16;" :: "r"(dst), "l"(src))
#define CP_COMMIT() asm volatile("cp.async.commit_group;")
#define CP_WAIT1()  asm volatile("cp.async.wait_group 1;")
#define CP_WAIT0()  asm volatile("cp.async.wait_group 0;")

#define LDSM4(r0, r1, r2, r3, addr) \
    asm volatile("ldmatrix.sync.aligned.m8n8.x4.shared.b16 {%0,%1,%2,%3}, [%4];" \
        : "=r"(r0), "=r"(r1), "=r"(r2), "=r"(r3) : "r"(addr))

#define MMA16816(d, a, b0, b1) \
    asm volatile("mma.sync.aligned.m16n8k16.row.col.f32.f16.f16.f32 " \
        "{%0,%1,%2,%3}, {%4,%5,%6,%7}, {%8,%9}, {%0,%1,%2,%3};" \
        : "+f"(d[0]), "+f"(d[1]), "+f"(d[2]), "+f"(d[3]) \
        : "r"(a[0]), "r"(a[1]), "r"(a[2]), "r"(a[3]), "r"(b0), "r"(b1))

// ---------------- merged setup + weight prep ----------------
#define B1_ELEMS (NBU * D_INP)
#define W2_ELEMS (D_OUTP * KCAT)
__global__ void k_prep(const float* __restrict__ nu_log,
                       const float* __restrict__ theta_log,
                       const float* __restrict__ gamma_log,
                       const float* __restrict__ Br,
                       const float* __restrict__ Bi,
                       const float* __restrict__ Cr,
                       const float* __restrict__ Ci,
                       const float* __restrict__ Dm) {
    int idx = blockIdx.x * blockDim.x + threadIdx.x;
    if (idx < N_ST) {
        int n = idx;
        float lm = expf(-expf(nu_log[n]));
        float th = expf(theta_log[n]);
        float2 lam = make_float2(lm * cosf(th), lm * sinf(th));
        g_lam[n] = lam;
        float2 p = lam;
#pragma unroll
        for (int i = 0; i < 6; i++) {
            float2 q;
            q.x = p.x * p.x - p.y * p.y;
            q.y = 2.0f * p.x * p.y;
            p = q;
        }
        g_lam64[n] = p;                      // lam^64
        float2 q;
        q.x = p.x * p.x - p.y * p.y;
        q.y = 2.0f * p.x * p.y;
        g_lamL[n] = q;                       // lam^128
    } else if (idx < N_ST + B1_ELEMS) {
        int j = idx - N_ST;
        int nn = j / D_INP, i = j % D_INP;
        int n = nn >> 1;
        float g = expf(gamma_log[n]);
        float v = g * (((nn & 1) == 0) ? Br[n * D_INP + i] : Bi[n * D_INP + i]);
        g_B1[j] = __float2half_rn(v);
    } else if (idx < N_ST + B1_ELEMS + W2_ELEMS) {
        int j = idx - N_ST - B1_ELEMS;
        int o = j / KCAT, k = j % KCAT;
        float v;
        if (k < NBU) {
            int n = k >> 1;
            v = ((k & 1) == 0) ? 2.0f * Cr[o * N_ST + n] : -2.0f * Ci[o * N_ST + n];
        } else {
            v = Dm[o * D_INP + (k - NBU)];
        }
        g_W2[j] = __float2half_rn(v);
    }
}

__global__ void k_cvtU(const float* __restrict__ u) {
    int idx = blockIdx.x * blockDim.x + threadIdx.x;
    if (idx >= M_TOT * D_INP / 4) return;
    int m = idx / (D_INP / 4), i = (idx % (D_INP / 4)) * 4;
    float4 v = *(const float4*)(u + (size_t)m * D_INP + i);
    __half2 h0 = __floats2half2_rn(v.x, v.y);
    __half2 h1 = __floats2half2_rn(v.z, v.w);
    __half2* dst = (__half2*)(g_A2 + (size_t)m * KCAT + NBU + i);
    dst[0] = h0;
    dst[1] = h1;
}

// ---------------- GEMM mainloop: CTA 128(M) x 128(N), BK=64, 256 threads ----------------
// 8 warps as 2(m) x 4(n); warp tile 64x32; mma.m16n8k16; acc[4][4][4].
// 3-stage cp.async pipeline (2 in flight), ONE __syncthreads per 64-wide k-chunk.
#define NTHREADS 256
#define BK       64
#define PADK     72                       // padded k-stride (elems) -> 144 B rows
#define TILE_T_B (128 * PADK * 2)         // 18432 B per tile (A or B)
#define STAGE_B  (2 * TILE_T_B)           // 36864 B
#define STAGES   3
#define SMEM_GEMM (STAGES * STAGE_B)      // 110592 B

__device__ __forceinline__ void gemm_mainloop(
    uint32_t sb, const __half* A0, const __half* B0,
    int K, int lda, int ldb, float acc[4][4][4],
    int tid, int wm, int wn, int lid) {

    const int NC = K / BK;

    auto issue_load = [&](int c) {
        const int s = c % STAGES;
        const uint32_t stb = sb + s * STAGE_B;
        const int k0 = c * BK;
#pragma unroll
        for (int r = 0; r < 4; r++) {                // A: 1024 chunks of 16B
            int idx = tid + r * NTHREADS;
            int row = idx >> 3, ch = idx & 7;
            uint32_t soff = (uint32_t)(row * (PADK * 2) + ch * 16);
            CP_ASYNC16(stb + soff, A0 + (size_t)row * lda + k0 + ch * 8);
        }
#pragma unroll
        for (int r = 0; r < 4; r++) {                // B: 1024 chunks
            int idx = tid + r * NTHREADS;
            int row = idx >> 3, ch = idx & 7;
            uint32_t soff = (uint32_t)(row * (PADK * 2) + ch * 16);
            CP_ASYNC16(stb + TILE_T_B + soff, B0 + (size_t)row * ldb + k0 + ch * 8);
        }
        CP_COMMIT();
    };

    const int aRow = lid & 15;
    const int aCol = (lid >> 4) << 3;
    const int bRow = (lid & 7) + ((lid >> 4) << 3);
    const int bCol = ((lid >> 3) & 1) << 3;

    issue_load(0);
    issue_load(1);

    for (int c = 0; c < NC; c++) {
        CP_WAIT1();
        __syncthreads();                   // single barrier per k-chunk
        if (c + 2 < NC) issue_load(c + 2);
        else            CP_COMMIT();       // keep group-count invariant

        const uint32_t stb = sb + (c % STAGES) * STAGE_B;
        const uint32_t sA = stb;
        const uint32_t sB = stb + TILE_T_B;

#pragma unroll
        for (int kk = 0; kk < BK; kk += 16) {
            uint32_t a[4][4], b[2][4];
#pragma unroll
            for (int mf = 0; mf < 4; mf++) {
                uint32_t ad = sA + (uint32_t)((wm * 64 + mf * 16 + aRow) * (PADK * 2) + (kk + aCol) * 2);
                LDSM4(a[mf][0], a[mf][1], a[mf][2], a[mf][3], ad);
            }
#pragma unroll
            for (int p = 0; p < 2; p++) {
                uint32_t bd = sB + (uint32_t)((wn * 32 + p * 16 + bRow) * (PADK * 2) + (kk + bCol) * 2);
                LDSM4(b[p][0], b[p][1], b[p][2], b[p][3], bd);
            }
#pragma unroll
            for (int mf = 0; mf < 4; mf++)
#pragma unroll
                for (int nf = 0; nf < 4; nf++)
                    MMA16816(acc[mf][nf], a[mf], b[nf >> 1][(nf & 1) * 2], b[nf >> 1][(nf & 1) * 2 + 1]);
        }
    }
    CP_WAIT0();
}

// ---------------- GEMM1 + fused chunk-local scan (64 states per tile) ----------------
#define SCAN_STRIDE 136

__global__ __launch_bounds__(NTHREADS, 2)
void gemm1_scan(const __half* __restrict__ A,
                const __half* __restrict__ B) {
    extern __shared__ char smem[];
    const uint32_t sb = smem_u32(smem);
    const int tid = threadIdx.x;
    const int wid = tid >> 5, lid = tid & 31;
    const int m0 = blockIdx.y * 128;
    const int n0 = blockIdx.x * 128;
    const int wm = wid >> 2, wn = wid & 3;

    float acc[4][4][4];
#pragma unroll
    for (int i = 0; i < 4; i++)
#pragma unroll
        for (int j = 0; j < 4; j++)
#pragma unroll
            for (int q = 0; q < 4; q++) acc[i][j][q] = 0.0f;

    gemm_mainloop(sb, A + (size_t)m0 * KCAT, B + (size_t)n0 * D_INP,
                  D_INP, KCAT, D_INP, acc, tid, wm, wn, lid);

    __syncthreads();            // drain: pipeline smem dead, reuse for scan buffer

    float* sc = (float*)smem;   // [128][SCAN_STRIDE]
    const int gid = lid >> 2, tig = lid & 3;
#pragma unroll
    for (int mf = 0; mf < 4; mf++) {
        const int row = wm * 64 + mf * 16 + gid;
#pragma unroll
        for (int nf = 0; nf < 4; nf++) {
            const int col = wn * 32 + nf * 8 + tig * 2;
            *(float2*)(sc + row * SCAN_STRIDE + col) =
                make_float2(acc[mf][nf][0], acc[mf][nf][1]);
            *(float2*)(sc + (row + 8) * SCAN_STRIDE + col) =
                make_float2(acc[mf][nf][2], acc[mf][nf][3]);
        }
    }
    __syncthreads();

    // chunk-local complex scan: 64 complex pairs in this tile
    if (tid < 64) {
        const int np = (n0 >> 1) + tid;         // global state index
        const float2 lam = g_lam[np];
        const int b = m0 >> 12;                 // / T_LEN
        const int c = (m0 & (T_LEN - 1)) >> 7;  // / CHUNK
        float xr = 0.0f, xi = 0.0f;
        __half* out = g_A2 + (size_t)m0 * KCAT + 2 * np;
#pragma unroll 4
        for (int t = 0; t < CHUNK; t++) {
            float2 bu = *(const float2*)(sc + t * SCAN_STRIDE + 2 * tid);
            float nxr = fmaf(lam.x, xr, fmaf(-lam.y, xi, bu.x));
            float nxi = fmaf(lam.x, xi, fmaf(lam.y, xr, bu.y));
            xr = nxr; xi = nxi;
            *(__half2*)(out + (size_t)t * KCAT) = __floats2half2_rn(xr, xi);
        }
        g_F[(b * NCHUNK + c) * N_ST + np] = make_float2(xr, xi);
    }
}

// ---------------- GEMM2: y[M,256] = A2 @ W2^T ----------------
__global__ __launch_bounds__(NTHREADS, 2)
void gemm2_out(const __half* __restrict__ A,
               const __half* __restrict__ B,
               float* __restrict__ C) {
    extern __shared__ char smem[];
    const uint32_t sb = smem_u32(smem);
    const int tid = threadIdx.x;
    const int wid = tid >> 5, lid = tid & 31;
    const int m0 = blockIdx.y * 128;
    const int n0 = blockIdx.x * 128;
    const int wm = wid >> 2, wn = wid & 3;

    float acc[4][4][4];
#pragma unroll
    for (int i = 0; i < 4; i++)
#pragma unroll
        for (int j = 0; j < 4; j++)
#pragma unroll
            for (int q = 0; q < 4; q++) acc[i][j][q] = 0.0f;

    gemm_mainloop(sb, A + (size_t)m0 * KCAT, B + (size_t)n0 * KCAT,
                  KCAT, KCAT, KCAT, acc, tid, wm, wn, lid);

    const int gid = lid >> 2, tig = lid & 3;
#pragma unroll
    for (int mf = 0; mf < 4; mf++) {
        const int row = m0 + wm * 64 + mf * 16 + gid;
#pragma unroll
        for (int nf = 0; nf < 4; nf++) {
            const int col = n0 + wn * 32 + nf * 8 + tig * 2;
            *(float2*)(C + (size_t)row * D_OUTP + col) =
                make_float2(acc[mf][nf][0], acc[mf][nf][1]);
            *(float2*)(C + (size_t)(row + 8) * D_OUTP + col) =
                make_float2(acc[mf][nf][2], acc[mf][nf][3]);
        }
    }
}

// ---------------- chunk-level prefix: Kogge-Stone warp scan ----------------
__global__ void k_chunk_prefix() {
    int gid = blockIdx.x * blockDim.x + threadIdx.x;
    int w = gid >> 5;                       // (b, n) index
    int lane = gid & 31;
    if (w >= B_SZ * N_ST) return;
    int n = w & (N_ST - 1);
    int b = w >> 9;

    float2 lamL = g_lamL[n];
    float2 f = g_F[(b * NCHUNK + lane) * N_ST + n];
    float ar = lamL.x, ai = lamL.y;         // A (lam^128)
    float br = f.x,    bi = f.y;            // B

#pragma unroll
    for (int d = 1; d < 32; d <<= 1) {
        float par = __shfl_up_sync(0xFFFFFFFFu, ar, d);
        float pai = __shfl_up_sync(0xFFFFFFFFu, ai, d);
        float pbr = __shfl_up_sync(0xFFFFFFFFu, br, d);
        float pbi = __shfl_up_sync(0xFFFFFFFFu, bi, d);
        if (lane >= d) {
            float nbr = ar * pbr - ai * pbi + br;
            float nbi = ar * pbi + ai * pbr + bi;
            float nar = ar * par - ai * pai;
            float nai = ar * pai + ai * par;
            ar = nar; ai = nai; br = nbr; bi = nbi;
        }
    }
    float cr = __shfl_up_sync(0xFFFFFFFFu, br, 1);
    float ci = __shfl_up_sync(0xFFFFFFFFu, bi, 1);
    if (lane == 0) { cr = 0.0f; ci = 0.0f; }
    g_carry[(b * NCHUNK + lane) * N_ST + n] = make_float2(cr, ci);
}

// ---------------- carry correction: x_t += lam^{t+1} * carry ----------------
__global__ void k_correct() {
    int id = blockIdx.x * blockDim.x + threadIdx.x;
    if (id >= B_SZ * NCHUNK * (N_ST / 2) * 2) return;
    int sp = id & (N_ST / 2 - 1);             // state pair 0..255
    int h  = (id >> 8) & 1;                   // t-half
    int c  = (id >> 9) & (NCHUNK - 1);
    int b  = id >> 14;
    if (c == 0) return;                       // carry is zero for chunk 0
    const int np0 = 2 * sp, np1 = 2 * sp + 1;
    const int cbase = (b * NCHUNK + c) * N_ST;
    float2 ca = g_carry[cbase + np0];
    float2 cb = g_carry[cbase + np1];
    float2 la = g_lam[np0];
    float2 lb = g_lam[np1];
    float ar = ca.x, ai = ca.y;
    float br = cb.x, bi = cb.y;
    if (h) {                                   // seed with lam^64
        float2 pa = g_lam64[np0], pb = g_lam64[np1];
        float t0 = ar * pa.x - ai * pa.y;
        ai = ar * pa.y + ai * pa.x; ar = t0;
        float t1 = br * pb.x - bi * pb.y;
        bi = br * pb.y + bi * pb.x; br = t1;
    }
    __half2* xp = (__half2*)(g_A2 + ((size_t)(b * T_LEN + c * CHUNK + h * 64)) * KCAT + 4 * sp);
    const int stride2 = KCAT / 2;             // __half2 stride per t
#pragma unroll 4
    for (int t = 0; t < 64; t++) {
        float nar = ar * la.x - ai * la.y;
        float nai = ar * la.y + ai * la.x;
        ar = nar; ai = nai;
        float nbr = br * lb.x - bi * lb.y;
        float nbi = br * lb.y + bi * lb.x;
        br = nbr; bi = nbi;
        uint2* up = (uint2*)(xp + (size_t)t * stride2);
        uint2 raw = *up;
        __half2 v0 = *(__half2*)&raw.x;
        __half2 v1 = *(__half2*)&raw.y;
        float2 x0 = __half22float2(v0);
        float2 x1 = __half22float2(v1);
        __half2 o0 = __floats2half2_rn(x0.x + ar, x0.y + ai);
        __half2 o1 = __floats2half2_rn(x1.x + br, x1.y + bi);
        uint2 out;
        out.x = *(uint32_t*)&o0;
        out.y = *(uint32_t*)&o1;
        *up = out;
    }
}

// ---------------- launch ----------------
extern "C" void kernel_launch(void* const* d_in, const int* in_sizes, int n_in,
                              void* d_out, int out_size) {
    const float* u_in      = (const float*)d_in[0];
    const float* nu_log    = (const float*)d_in[1];
    const float* theta_log = (const float*)d_in[2];
    const float* gamma_log = (const float*)d_in[3];
    const float* B_real    = (const float*)d_in[4];
    const float* B_imag    = (const float*)d_in[5];
    const float* C_real    = (const float*)d_in[6];
    const float* C_imag    = (const float*)d_in[7];
    const float* Dm        = (const float*)d_in[8];
    float* y = (float*)d_out;

    __half *a2, *b1, *w2;
    cudaGetSymbolAddress((void**)&a2, g_A2);
    cudaGetSymbolAddress((void**)&b1, g_B1);
    cudaGetSymbolAddress((void**)&w2, g_W2);

    cudaFuncSetAttribute(gemm1_scan,
                         cudaFuncAttributeMaxDynamicSharedMemorySize, SMEM_GEMM);
    cudaFuncSetAttribute(gemm2_out,
                         cudaFuncAttributeMaxDynamicSharedMemorySize, SMEM_GEMM);

    // merged setup + weight prep, then u conversion
    k_prep<<<(N_ST + B1_ELEMS + W2_ELEMS + 255) / 256, 256>>>(
        nu_log, theta_log, gamma_log, B_real, B_imag, C_real, C_imag, Dm);
    k_cvtU<<<(M_TOT * D_INP / 4 + 255) / 256, 256>>>(u_in);

    // GEMM1 + chunk-local scan: writes X_local (fp16) into A2 and chunk finals
    {
        dim3 grid(NBU / 128, M_TOT / 128);
        gemm1_scan<<<grid, NTHREADS, SMEM_GEMM>>>(a2 + NBU, b1);
    }

    // chunk prefix (warp scan) + carry correction
    k_chunk_prefix<<<(B_SZ * N_ST * 32 + 255) / 256, 256>>>();
    k_correct<<<(B_SZ * NCHUNK * N_ST + 255) / 256, 256>>>();

    // GEMM 2: y[M, 256] = [X | u] @ W2^T, K=1280
    {
        dim3 grid(D_OUTP / 128, M_TOT / 128);
        gemm2_out<<<grid, NTHREADS, SMEM_GEMM>>>(a2, w2, y);
    }
}